// round 3
// baseline (speedup 1.0000x reference)
#include <cuda_runtime.h>

#define CIN   32
#define COUT  32
#define HDIM  64
#define WDIM  64
#define TILE  8
#define NTHR  256

// wp_s: per-cp row of 322 words; lane c at [cp*322 + c*10 + k], k=0..8, k=9 zero pad.
//   LDS.64 k-pairs: lane stride 10 -> 10l mod 32 distinct per 16-lane phase (conflict-free).
#define WPROW 322
// x_dup: duplicated {v,v} halo tile, row stride 24 words, channel stride 240.
//   halo col jj (0..9) at words 2jj+2 .. 2jj+3; pixel-pair pp quad at words 4pp+4 (16B aligned).
#define XDROW 24
#define XDCH  240
// x_plain: scalar halo tile, row stride 12, channel stride 121 (odd -> lane=c reads conflict-free)
#define XPCH  121

#define WP_WORDS (CIN * WPROW)   // 10304
#define XD_WORDS (CIN * XDCH)    // 7680
#define XP_WORDS (CIN * XPCH)    // 3872
#define SMEM_FLOATS (WP_WORDS + XD_WORDS + XP_WORDS)   // 21856 words = 87424 B

typedef unsigned long long ull;

__device__ __forceinline__ ull pack2(float lo, float hi) {
    ull r;
    asm("mov.b64 %0, {%1, %2};" : "=l"(r) : "f"(lo), "f"(hi));
    return r;
}
__device__ __forceinline__ void unpack2(ull v, float& lo, float& hi) {
    asm("mov.b64 {%0, %1}, %2;" : "=f"(lo), "=f"(hi) : "l"(v));
}
#define FFMA2(d, a, b, c) \
    asm("fma.rn.f32x2 %0, %1, %2, %3;" : "=l"(d) : "l"(a), "l"(b), "l"(c))
#define FMUL2(d, a, b) \
    asm("mul.rn.f32x2 %0, %1, %2;" : "=l"(d) : "l"(a), "l"(b))

__global__ __launch_bounds__(NTHR, 2)
void dyn_conv_kernel(const float* __restrict__ x,
                     const float* __restrict__ Wp,
                     const float* __restrict__ bp,
                     float* __restrict__ out)
{
    extern __shared__ float smem[];
    float* wp_s = smem;                     // non-duplicated weights, k-padded to 10
    float* xd_s = smem + WP_WORDS;          // duplicated x pairs (for LDS.128 broadcast)
    float* xp_s = xd_s + XD_WORDS;          // plain x (for epilogue scalar reads)

    const int bz  = blockIdx.z;
    const int b   = bz >> 5;                // batch
    const int o   = bz & 31;                // output channel
    const int tx0 = blockIdx.x * TILE;
    const int ty0 = blockIdx.y * TILE;
    const int tid = threadIdx.x;

    // ---- Stage Wp slice for this o: wp_s[cp*322 + c*10 + k] ----
    {
        const float* wpo = Wp + (size_t)o * 9216;
        #pragma unroll 4
        for (int i = tid; i < 9216; i += NTHR) {
            int j  = i >> 5;            // j = c*9 + k
            int cp = i & 31;
            int c  = j / 9;
            int k  = j - 9 * c;
            wp_s[cp * WPROW + c * 10 + k] = wpo[i];   // coalesced read
        }
        // zero the k=9 pad slots
        for (int i = tid; i < 1024; i += NTHR) {
            int c  = i & 31;
            int cp = i >> 5;
            wp_s[cp * WPROW + c * 10 + 9] = 0.0f;
        }
    }

    // ---- Stage x halo tile (both duplicated and plain copies) ----
    {
        const float* xb = x + (size_t)b * CIN * HDIM * WDIM;
        #pragma unroll 4
        for (int i = tid; i < CIN * 100; i += NTHR) {
            int c  = i / 100;
            int rr = i - c * 100;
            int r  = rr / 10;
            int jj = rr - r * 10;       // halo col: x-offset jj-1
            int yy = ty0 + r - 1;
            int xx = tx0 + jj - 1;
            float v = 0.0f;
            if (yy >= 0 && yy < HDIM && xx >= 0 && xx < WDIM)
                v = xb[(c * HDIM + yy) * WDIM + xx];
            xp_s[c * XPCH + r * 12 + jj] = v;
            *(ull*)(xd_s + c * XDCH + r * XDROW + 2 * jj + 2) = pack2(v, v);
        }
    }
    __syncthreads();

    const int warp = tid >> 5;    // tile row (0..7)
    const int lane = tid & 31;    // lane = Cin index c

    // ---- Accumulators: acc2[kk][p] = {dyn_w(k=2kk), dyn_w(k=2kk+1)} for pixel p ----
    ull acc2[5][8];
    {
        const float* bprow = bp + o * 288 + lane * 9;
        #pragma unroll
        for (int kk = 0; kk < 4; kk++) {
            ull bv = pack2(bprow[2 * kk], bprow[2 * kk + 1]);
            #pragma unroll
            for (int p = 0; p < 8; p++) acc2[kk][p] = bv;
        }
        ull b8 = pack2(bprow[8], 0.0f);
        #pragma unroll
        for (int p = 0; p < 8; p++) acc2[4][p] = b8;
    }

    // ---- Mainloop: pred GEMM slice over input channels cp ----
    {
        const float* wlane = wp_s + lane * 10;
        const float* xwarp = xd_s + (1 + warp) * XDROW + 4;
        #pragma unroll 4
        for (int cp = 0; cp < CIN; cp++) {
            // x pixel-pair quads: {x_2pp,x_2pp,x_2pp+1,x_2pp+1} (broadcast LDS.128)
            const ulonglong2* xq = (const ulonglong2*)(xwarp + cp * XDCH);
            ulonglong2 xv0 = xq[0], xv1 = xq[1], xv2 = xq[2], xv3 = xq[3];
            // weight k-pairs (conflict-free LDS.64)
            const ull* wv = (const ull*)(wlane + cp * WPROW);
            ull w0 = wv[0], w1 = wv[1], w2 = wv[2], w3 = wv[3], w4 = wv[4];

            #define STEP(kk, w)                              \
                FFMA2(acc2[kk][0], w, xv0.x, acc2[kk][0]);   \
                FFMA2(acc2[kk][1], w, xv0.y, acc2[kk][1]);   \
                FFMA2(acc2[kk][2], w, xv1.x, acc2[kk][2]);   \
                FFMA2(acc2[kk][3], w, xv1.y, acc2[kk][3]);   \
                FFMA2(acc2[kk][4], w, xv2.x, acc2[kk][4]);   \
                FFMA2(acc2[kk][5], w, xv2.y, acc2[kk][5]);   \
                FFMA2(acc2[kk][6], w, xv3.x, acc2[kk][6]);   \
                FFMA2(acc2[kk][7], w, xv3.y, acc2[kk][7]);
            STEP(0, w0) STEP(1, w1) STEP(2, w2) STEP(3, w3) STEP(4, w4)
            #undef STEP
        }
    }

    // ---- c-norm: butterfly all-reduce of squares over lanes, per (k, p) ----
    #pragma unroll
    for (int kk = 0; kk < 5; kk++) {
        #pragma unroll
        for (int p = 0; p < 8; p++) {
            ull sq;
            FMUL2(sq, acc2[kk][p], acc2[kk][p]);
            float s0, s1;
            unpack2(sq, s0, s1);
            s0 += __shfl_xor_sync(0xffffffffu, s0, 16);
            s1 += __shfl_xor_sync(0xffffffffu, s1, 16);
            s0 += __shfl_xor_sync(0xffffffffu, s0, 8);
            s1 += __shfl_xor_sync(0xffffffffu, s1, 8);
            s0 += __shfl_xor_sync(0xffffffffu, s0, 4);
            s1 += __shfl_xor_sync(0xffffffffu, s1, 4);
            s0 += __shfl_xor_sync(0xffffffffu, s0, 2);
            s1 += __shfl_xor_sync(0xffffffffu, s1, 2);
            s0 += __shfl_xor_sync(0xffffffffu, s0, 1);
            s1 += __shfl_xor_sync(0xffffffffu, s1, 1);
            // v / max(sqrt(s),1e-12) == v * rsqrt(max(s,1e-24)); k=9 half: 0*big = 0
            float r0 = rsqrtf(fmaxf(s0, 1e-24f));
            float r1 = rsqrtf(fmaxf(s1, 1e-24f));
            FMUL2(acc2[kk][p], acc2[kk][p], pack2(r0, r1));
        }
    }

    // ---- k-norm + patch contraction + dynamic bias + c-reduce ----
    const float wpb = Wp[(size_t)(9216 + o) * 32 + lane];
    const float bpo = bp[9216 + o];
    const float* xlane = xp_s + lane * XPCH;

    #pragma unroll
    for (int p = 0; p < 8; p++) {
        // sum of squares over k (k=9 pad contributes 0)
        ull s2 = pack2(0.0f, 0.0f);
        #pragma unroll
        for (int kk = 0; kk < 5; kk++)
            FFMA2(s2, acc2[kk][p], acc2[kk][p], s2);
        float sa, sb;
        unpack2(s2, sa, sb);
        float inv2 = rsqrtf(fmaxf(sa + sb, 1e-24f));

        float a[10];
        #pragma unroll
        for (int kk = 0; kk < 5; kk++) unpack2(acc2[kk][p], a[2 * kk], a[2 * kk + 1]);

        // unscaled contraction, inv2 factored out
        float t = 0.0f;
        #pragma unroll
        for (int k = 0; k < 9; k++) {
            int dy = k / 3, dx = k - 3 * dy;
            float pv = xlane[(warp + dy) * 12 + (p + dx)];   // conflict-free (odd stride)
            t = fmaf(a[k], pv, t);
        }
        float res = fmaf(t, inv2, wpb * xlane[(warp + 1) * 12 + (p + 1)]);

        res += __shfl_xor_sync(0xffffffffu, res, 16);
        res += __shfl_xor_sync(0xffffffffu, res, 8);
        res += __shfl_xor_sync(0xffffffffu, res, 4);
        res += __shfl_xor_sync(0xffffffffu, res, 2);
        res += __shfl_xor_sync(0xffffffffu, res, 1);
        if (lane == 0) {
            int yy = ty0 + warp;
            int xx = tx0 + p;
            out[(((size_t)b * COUT + o) * HDIM + yy) * WDIM + xx] = res + bpo;
        }
    }
}

extern "C" void kernel_launch(void* const* d_in, const int* in_sizes, int n_in,
                              void* d_out, int out_size)
{
    const float* x  = (const float*)d_in[0];   // (2, 32, 64, 64)
    const float* Wp = (const float*)d_in[1];   // (9248, 32)
    const float* bp = (const float*)d_in[2];   // (9248,)
    float* out = (float*)d_out;                // (2, 32, 64, 64)

    const size_t smem_bytes = SMEM_FLOATS * sizeof(float);   // 87424 B
    cudaFuncSetAttribute(dyn_conv_kernel,
                         cudaFuncAttributeMaxDynamicSharedMemorySize,
                         (int)smem_bytes);

    dim3 grid(WDIM / TILE, HDIM / TILE, 2 * COUT);  // (8, 8, 64)
    dyn_conv_kernel<<<grid, NTHR, smem_bytes>>>(x, Wp, bp, out);
}

// round 5
// speedup vs baseline: 1.3367x; 1.3367x over previous
#include <cuda_runtime.h>
#include <cuda_bf16.h>
#include <cstdint>

#define CIN   32
#define COUT  32
#define HDIM  64
#define WDIM  64
#define TM    8       // tile rows (y)
#define TN    16      // tile cols (x)
#define NTHR  512
#define RS    18      // xs row stride (words)
#define XCH   185     // xs channel stride (words)
#define ASTR  36      // A/B row stride in 32-bit words (144B)
#define DSTR  146     // Dbuf row stride (words)

// smem byte offsets
#define OFF_A    0               // 128 * 144               = 18432
#define OFF_B    18432           // 288 * 144               = 41472
#define OFF_XS   59904           // 32 * 185 * 4            = 23680
#define OFF_DB   83584           // 128 * 146 * 4           = 74752
#define OFF_S1   158336          // 2 * 128 * 12 * 4        = 12288
#define OFF_BPS  170624          // 288 * 4                 = 1152
#define OFF_WPB  171776          // 32 * 4                  = 128
#define OFF_OUT  171904          // 2 * 128 * 4             = 1024
#define SMEM_BYTES 172928

typedef unsigned int u32;

__device__ __forceinline__ void mma16816(float* d, const u32* a, const u32* b) {
    asm volatile(
        "mma.sync.aligned.m16n8k16.row.col.f32.bf16.bf16.f32 "
        "{%0,%1,%2,%3}, {%4,%5,%6,%7}, {%8,%9}, {%0,%1,%2,%3};"
        : "+f"(d[0]), "+f"(d[1]), "+f"(d[2]), "+f"(d[3])
        : "r"(a[0]), "r"(a[1]), "r"(a[2]), "r"(a[3]), "r"(b[0]), "r"(b[1]));
}

__global__ __launch_bounds__(NTHR, 1)
void dyn_conv_hmma(const float* __restrict__ x,
                   const float* __restrict__ Wp,
                   const float* __restrict__ bp,
                   float* __restrict__ out)
{
    extern __shared__ char sm[];
    u32*   Aw  = (u32*)(sm + OFF_A);
    u32*   Bw  = (u32*)(sm + OFF_B);
    float* xs  = (float*)(sm + OFF_XS);
    float* Db  = (float*)(sm + OFF_DB);
    float* S1  = (float*)(sm + OFF_S1);
    float* bps = (float*)(sm + OFF_BPS);
    float* wpb = (float*)(sm + OFF_WPB);
    float* ob  = (float*)(sm + OFF_OUT);

    const int bz = blockIdx.z;
    const int b  = bz >> 5;
    const int o  = bz & 31;
    const int x0 = blockIdx.x * TN;
    const int y0 = blockIdx.y * TM;
    const int tid  = threadIdx.x;
    const int wid  = tid >> 5;
    const int lane = tid & 31;
    const int g = lane >> 2;      // fragment group (row / n)
    const int q = lane & 3;       // fragment quad id
    const int mt = wid & 7;       // m-tile (pixel-row group): pixels mt*16..mt*16+15
    const int ng = wid >> 3;      // c-group: c in [16*ng, 16*ng+16)

    // ================= Staging =================
    // B: Wp slice for o, permuted rows n' = k*32 + c, bf16 hi|lo (hi words 0..15, lo 16..31)
    {
        const float* wpo = Wp + (size_t)o * 9216;
        #pragma unroll 2
        for (int i = tid; i < 9216; i += NTHR) {
            int n  = i >> 5;
            int cp = i & 31;
            int c  = n / 9;
            int k  = n - 9 * c;
            int np = k * 32 + c;
            float v = wpo[i];
            __nv_bfloat16 h = __float2bfloat16(v);
            __nv_bfloat16 l = __float2bfloat16(v - __bfloat162float(h));
            char* row = sm + OFF_B + np * 144;
            *(__nv_bfloat16*)(row + 2 * cp)      = h;
            *(__nv_bfloat16*)(row + 64 + 2 * cp) = l;
        }
    }
    // A: x center tile, row = pixel m (ty*16+tx), col = cp; bf16 hi|lo
    {
        const float* xb = x + (size_t)b * CIN * HDIM * WDIM;
        #pragma unroll 2
        for (int i = tid; i < 4096; i += NTHR) {
            int cp = i >> 7;
            int m  = i & 127;
            int yy = y0 + (m >> 4);
            int xx = x0 + (m & 15);
            float v = xb[(cp * HDIM + yy) * WDIM + xx];
            __nv_bfloat16 h = __float2bfloat16(v);
            __nv_bfloat16 l = __float2bfloat16(v - __bfloat162float(h));
            char* row = sm + OFF_A + m * 144;
            *(__nv_bfloat16*)(row + 2 * cp)      = h;
            *(__nv_bfloat16*)(row + 64 + 2 * cp) = l;
        }
    }
    // xs halo fp32: 32c x 10 x 18
    {
        const float* xb = x + (size_t)b * CIN * HDIM * WDIM;
        #pragma unroll 2
        for (int i = tid; i < 32 * 180; i += NTHR) {
            int c = i / 180;
            int j = i - c * 180;
            int r = j / RS;
            int cc = j - r * RS;
            float v = 0.0f;
            int yy = y0 + r - 1;
            int xx = x0 + cc - 1;
            if (yy >= 0 && yy < HDIM && xx >= 0 && xx < WDIM)
                v = xb[(c * HDIM + yy) * WDIM + xx];
            xs[c * XCH + r * RS + cc] = v;
        }
    }
    if (tid < 288) {
        int c = tid / 9, k = tid - 9 * c;
        bps[k * 32 + c] = bp[o * 288 + tid];
    }
    if (tid < 32) wpb[tid] = Wp[(size_t)(9216 + o) * 32 + tid];
    __syncthreads();

    // ================= GEMM + norms =================
    const int m0  = mt * 16;
    const int cb0 = 16 * ng;           // c base for this warp
    float acc[9][4];
    float s1p[2][9];
    #pragma unroll
    for (int r = 0; r < 2; r++)
        #pragma unroll
        for (int k = 0; k < 9; k++) s1p[r][k] = 0.0f;

    // A fragments (shared across phases): [ks][hi/lo][4]
    u32 afr[2][2][4];
    #pragma unroll
    for (int ks = 0; ks < 2; ks++)
        #pragma unroll
        for (int hl = 0; hl < 2; hl++) {
            int woff = q + 8 * ks + 16 * hl;
            afr[ks][hl][0] = Aw[(m0 + g) * ASTR + woff];
            afr[ks][hl][1] = Aw[(m0 + g + 8) * ASTR + woff];
            afr[ks][hl][2] = Aw[(m0 + g) * ASTR + woff + 4];
            afr[ks][hl][3] = Aw[(m0 + g + 8) * ASTR + woff + 4];
        }

    #pragma unroll 1
    for (int sp = 0; sp < 2; sp++) {      // phase = c-slot s'
        const int cb = cb0 + 8 * sp;
        // ---- MMA: 9 tiles, tile m has k=m, B rows n' = 32m + cb + (0..7) ----
        #pragma unroll
        for (int m = 0; m < 9; m++)
            #pragma unroll
            for (int e = 0; e < 4; e++) acc[m][e] = 0.0f;
        #pragma unroll
        for (int m = 0; m < 9; m++) {
            const u32* brow = Bw + (32 * m + cb + g) * ASTR;
            #pragma unroll
            for (int ks = 0; ks < 2; ks++) {
                u32 bh[2], bl[2];
                bh[0] = brow[q + 8 * ks];
                bh[1] = brow[q + 4 + 8 * ks];
                bl[0] = brow[q + 16 + 8 * ks];
                bl[1] = brow[q + 20 + 8 * ks];
                mma16816(acc[m], afr[ks][0], bh);   // hi*hi
                mma16816(acc[m], afr[ks][0], bl);   // hi*lo
                mma16816(acc[m], afr[ks][1], bh);   // lo*hi
            }
        }
        // ---- add predictor bias, accumulate s1[k] (biased) ----
        #pragma unroll
        for (int m = 0; m < 9; m++) {
            float b0 = bps[32 * m + cb + 2 * q];
            float b1 = bps[32 * m + cb + 2 * q + 1];
            acc[m][0] += b0; acc[m][1] += b1;
            acc[m][2] += b0; acc[m][3] += b1;
            s1p[0][m] = fmaf(acc[m][0], acc[m][0], s1p[0][m]);
            s1p[0][m] = fmaf(acc[m][1], acc[m][1], s1p[0][m]);
            s1p[1][m] = fmaf(acc[m][2], acc[m][2], s1p[1][m]);
            s1p[1][m] = fmaf(acc[m][3], acc[m][3], s1p[1][m]);
        }
        // ---- phase 0: park biased fragments in Dbuf (self-owned; no sync) ----
        if (sp == 0) {
            #pragma unroll
            for (int m = 0; m < 9; m++) {
                int col = m * 16 + 8 * ng + 2 * q;
                *(float2*)&Db[(m0 + g) * DSTR + col]     = make_float2(acc[m][0], acc[m][1]);
                *(float2*)&Db[(m0 + g + 8) * DSTR + col] = make_float2(acc[m][2], acc[m][3]);
            }
        }
    }

    // ---- s1 quad-reduce + cross-ng reduce via smem ----
    #pragma unroll
    for (int r = 0; r < 2; r++)
        #pragma unroll
        for (int k = 0; k < 9; k++) {
            float s = s1p[r][k];
            s += __shfl_xor_sync(0xffffffffu, s, 1);
            s += __shfl_xor_sync(0xffffffffu, s, 2);
            s1p[r][k] = s;
        }
    if (q == 0) {
        #pragma unroll
        for (int r = 0; r < 2; r++) {
            int m = m0 + g + 8 * r;
            #pragma unroll
            for (int k = 0; k < 9; k++)
                S1[(ng * 128 + m) * 12 + k] = s1p[r][k];
        }
    }
    __syncthreads();

    float inv1[2][9];
    #pragma unroll
    for (int r = 0; r < 2; r++) {
        int m = m0 + g + 8 * r;
        #pragma unroll
        for (int k = 0; k < 9; k++) {
            float t = S1[m * 12 + k] + S1[(128 + m) * 12 + k];
            inv1[r][k] = rsqrtf(fmaxf(t, 1e-24f));   // == 1/max(sqrt,1e-12)
        }
    }

    // ================= Epilogue (both phases) =================
    const int txr[2] = { g, g + 8 };    // tx for row r (ty = mt for both)
    float op[2] = { 0.0f, 0.0f };

    #pragma unroll
    for (int sp = 1; sp >= 0; sp--) {   // phase 1 first (still in regs), then reload 0
        const int cb = cb0 + 8 * sp;
        if (sp == 0) {
            #pragma unroll
            for (int m = 0; m < 9; m++) {
                int col = m * 16 + 8 * ng + 2 * q;
                float2 v0 = *(float2*)&Db[(m0 + g) * DSTR + col];
                float2 v1 = *(float2*)&Db[(m0 + g + 8) * DSTR + col];
                acc[m][0] = v0.x; acc[m][1] = v0.y;
                acc[m][2] = v1.x; acc[m][3] = v1.y;
            }
        }
        float s2[2][2] = {{0,0},{0,0}};   // [row][jj]
        float tp[2][2] = {{0,0},{0,0}};
        const int c0 = cb + 2 * q;        // jj=0 channel
        #pragma unroll
        for (int m = 0; m < 9; m++) {     // k = m
            const int dy = m / 3, dx = m - 3 * (m / 3);
            #pragma unroll
            for (int e = 0; e < 4; e++) {
                const int jj = e & 1, r = e >> 1;
                float d1 = acc[m][e] * inv1[r][m];
                s2[r][jj] = fmaf(d1, d1, s2[r][jj]);
                float pv = xs[(c0 + jj) * XCH + (mt + dy) * RS + (txr[r] + dx)];
                tp[r][jj] = fmaf(d1, pv, tp[r][jj]);
            }
        }
        #pragma unroll
        for (int r = 0; r < 2; r++)
            #pragma unroll
            for (int jj = 0; jj < 2; jj++) {
                int c = c0 + jj;
                float xc = xs[c * XCH + (mt + 1) * RS + (txr[r] + 1)];
                op[r] = fmaf(tp[r][jj], rsqrtf(fmaxf(s2[r][jj], 1e-24f)), op[r]);
                op[r] = fmaf(wpb[c], xc, op[r]);     // dynamic-bias partial
            }
    }

    // quad-reduce output partials, write per-ng buffers
    #pragma unroll
    for (int r = 0; r < 2; r++) {
        float s = op[r];
        s += __shfl_xor_sync(0xffffffffu, s, 1);
        s += __shfl_xor_sync(0xffffffffu, s, 2);
        op[r] = s;
    }
    if (q == 0) {
        ob[ng * 128 + m0 + g]     = op[0];
        ob[ng * 128 + m0 + g + 8] = op[1];
    }
    __syncthreads();

    if (tid < 128) {
        int m = tid;
        float r = ob[m] + ob[128 + m] + bp[9216 + o];
        out[(((size_t)b * COUT + o) * HDIM + (y0 + (m >> 4))) * WDIM + (x0 + (m & 15))] = r;
    }
}

extern "C" void kernel_launch(void* const* d_in, const int* in_sizes, int n_in,
                              void* d_out, int out_size)
{
    const float* x  = (const float*)d_in[0];   // (2, 32, 64, 64)
    const float* Wp = (const float*)d_in[1];   // (9248, 32)
    const float* bp = (const float*)d_in[2];   // (9248,)
    float* out = (float*)d_out;                // (2, 32, 64, 64)

    cudaFuncSetAttribute(dyn_conv_hmma,
                         cudaFuncAttributeMaxDynamicSharedMemorySize, SMEM_BYTES);

    dim3 grid(WDIM / TN, HDIM / TM, 2 * COUT);   // (4, 8, 64) -> 2048 CTAs
    dyn_conv_hmma<<<grid, NTHR, SMEM_BYTES>>>(x, Wp, bp, out);
}

// round 6
// speedup vs baseline: 2.0278x; 1.5170x over previous
#include <cuda_runtime.h>
#include <cuda_bf16.h>
#include <cstdint>

#define CIN   32
#define COUT  32
#define HDIM  64
#define WDIM  64
#define TM    8       // tile rows (y)
#define TN    16      // tile cols (x)
#define NTHR  256
#define RS    18      // xs row stride (words)
#define XCH   180     // xs channel stride (words): 2q*180 mod 32 = 8q -> conflict-free
#define ASTR  36      // A/B row stride in 32-bit words (144B)

// smem byte offsets
#define OFF_A    0               // 128 * 144  = 18432
#define OFF_B    18432           // 288 * 144  = 41472
#define OFF_XS   59904           // 32*180*4   = 23040
#define OFF_BPS  82944           // 288 * 4    = 1152
#define OFF_WPB  84096           // 32 * 4     = 128
#define SMEM_BYTES 84224

typedef unsigned int u32;

__device__ __forceinline__ void mma16816(float* d, const u32* a, u32 b0, u32 b1) {
    asm volatile(
        "mma.sync.aligned.m16n8k16.row.col.f32.bf16.bf16.f32 "
        "{%0,%1,%2,%3}, {%4,%5,%6,%7}, {%8,%9}, {%0,%1,%2,%3};"
        : "+f"(d[0]), "+f"(d[1]), "+f"(d[2]), "+f"(d[3])
        : "r"(a[0]), "r"(a[1]), "r"(a[2]), "r"(a[3]), "r"(b0), "r"(b1));
}

__global__ __launch_bounds__(NTHR, 2)
void dyn_conv_hmma(const float* __restrict__ x,
                   const float* __restrict__ Wp,
                   const float* __restrict__ bp,
                   float* __restrict__ out)
{
    extern __shared__ char sm[];
    u32*   Aw  = (u32*)(sm + OFF_A);
    u32*   Bw  = (u32*)(sm + OFF_B);
    float* xs  = (float*)(sm + OFF_XS);
    float* bps = (float*)(sm + OFF_BPS);
    float* wpb = (float*)(sm + OFF_WPB);

    const int bz = blockIdx.z;
    const int b  = bz >> 5;
    const int o  = bz & 31;
    const int x0 = blockIdx.x * TN;
    const int y0 = blockIdx.y * TM;
    const int tid  = threadIdx.x;
    const int wid  = tid >> 5;     // = mt, m-tile (pixel-row group)
    const int lane = tid & 31;
    const int g = lane >> 2;       // fragment group
    const int q = lane & 3;        // quad id
    const int mt = wid;
    const float bpo = bp[9216 + o];

    // ================= Staging =================
    // B: Wp slice for o, permuted rows n' = k*32 + c, bf16 hi|lo halves per 144B row
    {
        const float* wpo = Wp + (size_t)o * 9216;
        #pragma unroll 4
        for (int i = tid; i < 9216; i += NTHR) {
            int n  = i >> 5;
            int cp = i & 31;
            int c  = n / 9;
            int k  = n - 9 * c;
            float v = wpo[i];                       // coalesced
            __nv_bfloat16 h = __float2bfloat16(v);
            __nv_bfloat16 l = __float2bfloat16(v - __bfloat162float(h));
            char* row = sm + OFF_B + (k * 32 + c) * 144;
            *(__nv_bfloat16*)(row + 2 * cp)      = h;
            *(__nv_bfloat16*)(row + 64 + 2 * cp) = l;
        }
    }
    // A: x center tile, row = pixel m, col = cp; bf16 hi|lo
    {
        const float* xb = x + (size_t)b * CIN * HDIM * WDIM;
        #pragma unroll 4
        for (int i = tid; i < 4096; i += NTHR) {
            int cp = i >> 7;
            int m  = i & 127;
            int yy = y0 + (m >> 4);
            int xx = x0 + (m & 15);
            float v = xb[(cp * HDIM + yy) * WDIM + xx];
            __nv_bfloat16 h = __float2bfloat16(v);
            __nv_bfloat16 l = __float2bfloat16(v - __bfloat162float(h));
            char* row = sm + OFF_A + m * 144;
            *(__nv_bfloat16*)(row + 2 * cp)      = h;
            *(__nv_bfloat16*)(row + 64 + 2 * cp) = l;
        }
    }
    // xs halo fp32: 32 c x 10 rows x 18 cols
    {
        const float* xb = x + (size_t)b * CIN * HDIM * WDIM;
        #pragma unroll 4
        for (int i = tid; i < 32 * XCH; i += NTHR) {
            int c  = i / XCH;
            int j  = i - c * XCH;
            int r  = j / RS;
            int cc = j - r * RS;
            float v = 0.0f;
            int yy = y0 + r - 1;
            int xx = x0 + cc - 1;
            if (yy >= 0 && yy < HDIM && xx >= 0 && xx < WDIM)
                v = xb[(c * HDIM + yy) * WDIM + xx];
            xs[c * XCH + r * RS + cc] = v;
        }
    }
    for (int i = tid; i < 288; i += NTHR) {         // predictor bias, permuted
        int c = i / 9, k = i - 9 * c;
        bps[k * 32 + c] = bp[o * 288 + i];
    }
    if (tid < 32) wpb[tid] = Wp[(size_t)(9216 + o) * 32 + tid];
    __syncthreads();

    // ================= A fragments (persistent) =================
    const int m0 = mt * 16;
    u32 afr[2][2][4];      // [ks][hi/lo][4]
    #pragma unroll
    for (int ks = 0; ks < 2; ks++)
        #pragma unroll
        for (int hl = 0; hl < 2; hl++) {
            int woff = q + 8 * ks + 16 * hl;
            afr[ks][hl][0] = Aw[(m0 + g) * ASTR + woff];
            afr[ks][hl][1] = Aw[(m0 + g + 8) * ASTR + woff];
            afr[ks][hl][2] = Aw[(m0 + g) * ASTR + woff + 4];
            afr[ks][hl][3] = Aw[(m0 + g + 8) * ASTR + woff + 4];
        }

    // ================= Fused single pass over k =================
    const int txr0 = g, txr1 = g + 8;      // tx for the two acc rows
    float s2[2][8], tp[2][8];              // [row][c-slot = 2*oc + jj]
    #pragma unroll
    for (int r = 0; r < 2; r++)
        #pragma unroll
        for (int cl = 0; cl < 8; cl++) { s2[r][cl] = 0.0f; tp[r][cl] = 0.0f; }

    #pragma unroll
    for (int k = 0; k < 9; k++) {
        const int dy = k / 3, dx = k - 3 * (k / 3);

        // ---- 4 c-octet tiles for this k (independent accs -> MMA ILP) ----
        float accT[4][4];
        #pragma unroll
        for (int oc = 0; oc < 4; oc++)
            #pragma unroll
            for (int e = 0; e < 4; e++) accT[oc][e] = 0.0f;

        #pragma unroll
        for (int oc = 0; oc < 4; oc++) {
            const u32* brow = Bw + (32 * k + 8 * oc + g) * ASTR;
            #pragma unroll
            for (int ks = 0; ks < 2; ks++) {
                u32 bh0 = brow[q + 8 * ks];
                u32 bh1 = brow[q + 4 + 8 * ks];
                u32 bl0 = brow[q + 16 + 8 * ks];
                u32 bl1 = brow[q + 20 + 8 * ks];
                mma16816(accT[oc], afr[ks][0], bh0, bh1);   // hi*hi
                mma16816(accT[oc], afr[ks][0], bl0, bl1);   // hi*lo
                mma16816(accT[oc], afr[ks][1], bh0, bh1);   // lo*hi
            }
        }

        // ---- add predictor bias; per-thread c-partial of s1 ----
        float s1r0 = 0.0f, s1r1 = 0.0f;
        #pragma unroll
        for (int oc = 0; oc < 4; oc++) {
            float b0 = bps[32 * k + 8 * oc + 2 * q];
            float b1 = bps[32 * k + 8 * oc + 2 * q + 1];
            accT[oc][0] += b0; accT[oc][1] += b1;
            accT[oc][2] += b0; accT[oc][3] += b1;
            s1r0 = fmaf(accT[oc][0], accT[oc][0], s1r0);
            s1r0 = fmaf(accT[oc][1], accT[oc][1], s1r0);
            s1r1 = fmaf(accT[oc][2], accT[oc][2], s1r1);
            s1r1 = fmaf(accT[oc][3], accT[oc][3], s1r1);
        }
        // quad-reduce over q completes the 32-channel sum (all c live in-warp)
        s1r0 += __shfl_xor_sync(0xffffffffu, s1r0, 1);
        s1r0 += __shfl_xor_sync(0xffffffffu, s1r0, 2);
        s1r1 += __shfl_xor_sync(0xffffffffu, s1r1, 1);
        s1r1 += __shfl_xor_sync(0xffffffffu, s1r1, 2);
        float inv1r0 = rsqrtf(fmaxf(s1r0, 1e-24f));   // == 1/max(sqrt,1e-12)
        float inv1r1 = rsqrtf(fmaxf(s1r1, 1e-24f));

        // ---- scale by inv1, accumulate s2[c] and patch contraction ----
        #pragma unroll
        for (int oc = 0; oc < 4; oc++) {
            #pragma unroll
            for (int e = 0; e < 4; e++) {
                const int jj = e & 1, r = e >> 1;
                const int cl = 2 * oc + jj;
                const int c  = 8 * oc + 2 * q + jj;
                float d1 = accT[oc][e] * (r ? inv1r1 : inv1r0);
                s2[r][cl] = fmaf(d1, d1, s2[r][cl]);
                float pv = xs[c * XCH + (mt + dy) * RS + ((r ? txr1 : txr0) + dx)];
                tp[r][cl] = fmaf(d1, pv, tp[r][cl]);
            }
        }
    }

    // ================= k-norm + dynamic bias + output =================
    float op0 = 0.0f, op1 = 0.0f;
    #pragma unroll
    for (int oc = 0; oc < 4; oc++)
        #pragma unroll
        for (int jj = 0; jj < 2; jj++) {
            const int cl = 2 * oc + jj;
            const int c  = 8 * oc + 2 * q + jj;
            op0 = fmaf(tp[0][cl], rsqrtf(fmaxf(s2[0][cl], 1e-24f)), op0);
            op1 = fmaf(tp[1][cl], rsqrtf(fmaxf(s2[1][cl], 1e-24f)), op1);
            op0 = fmaf(wpb[c], xs[c * XCH + (mt + 1) * RS + (txr0 + 1)], op0);
            op1 = fmaf(wpb[c], xs[c * XCH + (mt + 1) * RS + (txr1 + 1)], op1);
        }
    op0 += __shfl_xor_sync(0xffffffffu, op0, 1);
    op0 += __shfl_xor_sync(0xffffffffu, op0, 2);
    op1 += __shfl_xor_sync(0xffffffffu, op1, 1);
    op1 += __shfl_xor_sync(0xffffffffu, op1, 2);

    if (q == 0) {
        float* orow = out + (((size_t)b * COUT + o) * HDIM + (y0 + mt)) * WDIM + x0;
        orow[txr0] = op0 + bpo;
        orow[txr1] = op1 + bpo;
    }
}

extern "C" void kernel_launch(void* const* d_in, const int* in_sizes, int n_in,
                              void* d_out, int out_size)
{
    const float* x  = (const float*)d_in[0];   // (2, 32, 64, 64)
    const float* Wp = (const float*)d_in[1];   // (9248, 32)
    const float* bp = (const float*)d_in[2];   // (9248,)
    float* out = (float*)d_out;                // (2, 32, 64, 64)

    cudaFuncSetAttribute(dyn_conv_hmma,
                         cudaFuncAttributeMaxDynamicSharedMemorySize, SMEM_BYTES);

    dim3 grid(WDIM / TN, HDIM / TM, 2 * COUT);   // (4, 8, 64) -> 2048 CTAs
    dyn_conv_hmma<<<grid, NTHR, SMEM_BYTES>>>(x, Wp, bp, out);
}

// round 7
// speedup vs baseline: 2.1011x; 1.0362x over previous
#include <cuda_runtime.h>
#include <cuda_bf16.h>
#include <cstdint>

#define CIN   32
#define COUT  32
#define HDIM  64
#define WDIM  64
#define TM    8       // tile rows (y)
#define TN    16      // tile cols (x)
#define NTHR  256
#define XST   40      // xs2 channel-dim stride (words): bank-pair = 4*col+q -> conflict-free

// smem byte offsets
#define OFF_A    0               // 32 blk * 512B  = 16384   (A fragments)
#define OFF_B    16384           // 72 blk * 512B  = 36864   (B fragments)
#define OFF_XS   53248           // 10*18*40*4     = 28800   (pixel-major halo)
#define OFF_BPS  82048           // 288 * 4        = 1152
#define OFF_WPB  83200           // 32 * 4         = 128
#define SMEM_BYTES 83328

typedef unsigned int u32;

__device__ __forceinline__ void mma16816(float* d, const uint4& a, u32 b0, u32 b1) {
    asm volatile(
        "mma.sync.aligned.m16n8k16.row.col.f32.bf16.bf16.f32 "
        "{%0,%1,%2,%3}, {%4,%5,%6,%7}, {%8,%9}, {%0,%1,%2,%3};"
        : "+f"(d[0]), "+f"(d[1]), "+f"(d[2]), "+f"(d[3])
        : "r"(a.x), "r"(a.y), "r"(a.z), "r"(a.w), "r"(b0), "r"(b1));
}
__device__ __forceinline__ u32 packbf(float v0, float v1, float& l0, float& l1) {
    __nv_bfloat16 h0 = __float2bfloat16(v0);
    __nv_bfloat16 h1 = __float2bfloat16(v1);
    l0 = v0 - __bfloat162float(h0);
    l1 = v1 - __bfloat162float(h1);
    return (u32)__bfloat16_as_ushort(h0) | ((u32)__bfloat16_as_ushort(h1) << 16);
}
__device__ __forceinline__ u32 packbf2(float v0, float v1) {
    return (u32)__bfloat16_as_ushort(__float2bfloat16(v0)) |
           ((u32)__bfloat16_as_ushort(__float2bfloat16(v1)) << 16);
}

__global__ __launch_bounds__(NTHR, 2)
void dyn_conv_hmma(const float* __restrict__ x,
                   const float* __restrict__ Wp,
                   const float* __restrict__ bp,
                   float* __restrict__ out)
{
    extern __shared__ char sm[];
    u32*   Afw = (u32*)(sm + OFF_A);
    u32*   Bfw = (u32*)(sm + OFF_B);
    float* xs  = (float*)(sm + OFF_XS);
    float* bps = (float*)(sm + OFF_BPS);
    float* wpb = (float*)(sm + OFF_WPB);

    const int bz = blockIdx.z;
    const int b  = bz >> 5;
    const int o  = bz & 31;
    const int x0 = blockIdx.x * TN;
    const int y0 = blockIdx.y * TM;
    const int tid  = threadIdx.x;
    const int lane = tid & 31;
    const int g = lane >> 2;
    const int q = lane & 3;
    const int mt = tid >> 5;       // warp = m-tile (pixel-row)
    const float bpo = bp[9216 + o];

    // ================= Staging =================
    // B fragments: blk=(k*4+oc)*2+ks, per lane 16B {bh0,bh1,bl0,bl1}
    {
        const float* wpo = Wp + (size_t)o * 9216;
        #pragma unroll 4
        for (u32 i = tid; i < 4608; i += NTHR) {
            u32 n = i >> 4, w16 = i & 15;
            u32 c = n / 9, k = n - 9u * c;
            float2 v = ((const float2*)(wpo + n * 32))[w16];   // coalesced
            float l0, l1;
            u32 hw = packbf(v.x, v.y, l0, l1);
            u32 lw = packbf2(l0, l1);
            u32 qq = w16 & 3, sel = (w16 >> 2) & 1, ks = w16 >> 3;
            u32 base = (((k * 4 + (c >> 3)) * 2 + ks) * 32 + ((c & 7) * 4 + qq)) * 4;
            Bfw[base + sel]     = hw;
            Bfw[base + 2 + sel] = lw;
        }
    }
    // A fragments: blk=(mt*2+ks)*2+hl, per lane 16B {a0,a1,a2,a3}
    {
        const float* xb = x + (size_t)b * CIN * HDIM * WDIM;
        #pragma unroll 4
        for (u32 i = tid; i < 2048; i += NTHR) {
            u32 m = i & 127, w16 = i >> 7;
            u32 yy = y0 + (m >> 4), xx = x0 + (m & 15);
            u32 src = yy * WDIM + xx;
            float v0 = xb[(2 * w16) * 4096 + src];      // coalesced
            float v1 = xb[(2 * w16 + 1) * 4096 + src];
            float l0, l1;
            u32 hw = packbf(v0, v1, l0, l1);
            u32 lw = packbf2(l0, l1);
            u32 qq = w16 & 3, sel = (w16 >> 2) & 1, ks = w16 >> 3;
            u32 mtt = m >> 4, r = (m >> 3) & 1, gg = m & 7;
            u32 w = sel * 2 + r;
            u32 base = ((mtt * 2 + ks) * 2) * 128 + (gg * 4 + qq) * 4 + w;
            Afw[base]       = hw;   // hl=0
            Afw[base + 128] = lw;   // hl=1
        }
    }
    // xs halo, pixel-major: word = (row*18+col)*40 + c
    {
        const float* xb = x + (size_t)b * CIN * HDIM * WDIM;
        #pragma unroll 4
        for (u32 i = tid; i < 5760; i += NTHR) {
            u32 c = i / 180u, j = i - 180u * c;
            u32 r = j / 18u, col = j - 18u * r;
            float v = 0.0f;
            int yy = (int)(y0 + r) - 1, xx = (int)(x0 + col) - 1;
            if (yy >= 0 && yy < HDIM && xx >= 0 && xx < WDIM)
                v = xb[(c * HDIM + yy) * WDIM + xx];
            xs[(r * 18 + col) * XST + c] = v;
        }
    }
    for (u32 i = tid; i < 288; i += NTHR) {       // predictor bias, permuted [k*32+c]
        u32 c = i / 9u, k = i - 9u * c;
        bps[k * 32 + c] = bp[o * 288 + i];
    }
    if (tid < 32) wpb[tid] = Wp[(size_t)(9216 + o) * 32 + tid];
    __syncthreads();

    // ================= A fragments (persistent) =================
    uint4 af[2][2];
    {
        const uint4* Aq = (const uint4*)(sm + OFF_A);
        #pragma unroll
        for (int ks = 0; ks < 2; ks++)
            #pragma unroll
            for (int hl = 0; hl < 2; hl++)
                af[ks][hl] = Aq[((mt * 2 + ks) * 2 + hl) * 32 + lane];
    }

    // ================= Fused single pass over k =================
    const uint4* Bq = (const uint4*)(sm + OFF_B);
    const int txr0 = g, txr1 = g + 8;
    float s2[2][8], tp[2][8];
    #pragma unroll
    for (int r = 0; r < 2; r++)
        #pragma unroll
        for (int cl = 0; cl < 8; cl++) { s2[r][cl] = 0.0f; tp[r][cl] = 0.0f; }

    #pragma unroll
    for (int k = 0; k < 9; k++) {
        const int dy = k / 3, dx = k - 3 * (k / 3);

        // accs initialized with predictor bias
        float accT[4][4];
        #pragma unroll
        for (int oc = 0; oc < 4; oc++) {
            float2 bv = *(const float2*)&bps[32 * k + 8 * oc + 2 * q];
            accT[oc][0] = bv.x; accT[oc][1] = bv.y;
            accT[oc][2] = bv.x; accT[oc][3] = bv.y;
        }
        // 4 independent c-octet tiles; 3-term bf16 split
        #pragma unroll
        for (int oc = 0; oc < 4; oc++) {
            #pragma unroll
            for (int ks = 0; ks < 2; ks++) {
                uint4 bb = Bq[((k * 4 + oc) * 2 + ks) * 32 + lane];  // LDS.128
                mma16816(accT[oc], af[ks][0], bb.x, bb.y);   // hi*hi
                mma16816(accT[oc], af[ks][0], bb.z, bb.w);   // hi*lo
                mma16816(accT[oc], af[ks][1], bb.x, bb.y);   // lo*hi
            }
        }
        // c-norm: per-thread partials + quad reduce (all 32 c live in-warp)
        float s1r0 = 0.0f, s1r1 = 0.0f;
        #pragma unroll
        for (int oc = 0; oc < 4; oc++) {
            s1r0 = fmaf(accT[oc][0], accT[oc][0], s1r0);
            s1r0 = fmaf(accT[oc][1], accT[oc][1], s1r0);
            s1r1 = fmaf(accT[oc][2], accT[oc][2], s1r1);
            s1r1 = fmaf(accT[oc][3], accT[oc][3], s1r1);
        }
        s1r0 += __shfl_xor_sync(0xffffffffu, s1r0, 1);
        s1r0 += __shfl_xor_sync(0xffffffffu, s1r0, 2);
        s1r1 += __shfl_xor_sync(0xffffffffu, s1r1, 1);
        s1r1 += __shfl_xor_sync(0xffffffffu, s1r1, 2);
        float inv1r0 = rsqrtf(fmaxf(s1r0, 1e-24f));   // == 1/max(sqrt,1e-12)
        float inv1r1 = rsqrtf(fmaxf(s1r1, 1e-24f));

        // scale by inv1, accumulate s2[c] and patch contraction (LDS.64 pv pairs)
        #pragma unroll
        for (int oc = 0; oc < 4; oc++) {
            float2 pv0 = *(const float2*)&xs[((mt + dy) * 18 + txr0 + dx) * XST + 8 * oc + 2 * q];
            float2 pv1 = *(const float2*)&xs[((mt + dy) * 18 + txr1 + dx) * XST + 8 * oc + 2 * q];
            float d00 = accT[oc][0] * inv1r0;
            float d01 = accT[oc][1] * inv1r0;
            float d10 = accT[oc][2] * inv1r1;
            float d11 = accT[oc][3] * inv1r1;
            s2[0][2 * oc]     = fmaf(d00, d00, s2[0][2 * oc]);
            s2[0][2 * oc + 1] = fmaf(d01, d01, s2[0][2 * oc + 1]);
            s2[1][2 * oc]     = fmaf(d10, d10, s2[1][2 * oc]);
            s2[1][2 * oc + 1] = fmaf(d11, d11, s2[1][2 * oc + 1]);
            tp[0][2 * oc]     = fmaf(d00, pv0.x, tp[0][2 * oc]);
            tp[0][2 * oc + 1] = fmaf(d01, pv0.y, tp[0][2 * oc + 1]);
            tp[1][2 * oc]     = fmaf(d10, pv1.x, tp[1][2 * oc]);
            tp[1][2 * oc + 1] = fmaf(d11, pv1.y, tp[1][2 * oc + 1]);
        }
    }

    // ================= k-norm + dynamic bias + output =================
    float op0 = 0.0f, op1 = 0.0f;
    #pragma unroll
    for (int oc = 0; oc < 4; oc++) {
        float2 wv  = *(const float2*)&wpb[8 * oc + 2 * q];
        float2 xc0 = *(const float2*)&xs[((mt + 1) * 18 + txr0 + 1) * XST + 8 * oc + 2 * q];
        float2 xc1 = *(const float2*)&xs[((mt + 1) * 18 + txr1 + 1) * XST + 8 * oc + 2 * q];
        op0 = fmaf(tp[0][2 * oc],     rsqrtf(fmaxf(s2[0][2 * oc],     1e-24f)), op0);
        op0 = fmaf(tp[0][2 * oc + 1], rsqrtf(fmaxf(s2[0][2 * oc + 1], 1e-24f)), op0);
        op1 = fmaf(tp[1][2 * oc],     rsqrtf(fmaxf(s2[1][2 * oc],     1e-24f)), op1);
        op1 = fmaf(tp[1][2 * oc + 1], rsqrtf(fmaxf(s2[1][2 * oc + 1], 1e-24f)), op1);
        op0 = fmaf(wv.x, xc0.x, op0);
        op0 = fmaf(wv.y, xc0.y, op0);
        op1 = fmaf(wv.x, xc1.x, op1);
        op1 = fmaf(wv.y, xc1.y, op1);
    }
    op0 += __shfl_xor_sync(0xffffffffu, op0, 1);
    op0 += __shfl_xor_sync(0xffffffffu, op0, 2);
    op1 += __shfl_xor_sync(0xffffffffu, op1, 1);
    op1 += __shfl_xor_sync(0xffffffffu, op1, 2);

    if (q == 0) {
        float* orow = out + (((size_t)b * COUT + o) * HDIM + (y0 + mt)) * WDIM + x0;
        orow[txr0] = op0 + bpo;
        orow[txr1] = op1 + bpo;
    }
}

extern "C" void kernel_launch(void* const* d_in, const int* in_sizes, int n_in,
                              void* d_out, int out_size)
{
    const float* x  = (const float*)d_in[0];   // (2, 32, 64, 64)
    const float* Wp = (const float*)d_in[1];   // (9248, 32)
    const float* bp = (const float*)d_in[2];   // (9248,)
    float* out = (float*)d_out;                // (2, 32, 64, 64)

    cudaFuncSetAttribute(dyn_conv_hmma,
                         cudaFuncAttributeMaxDynamicSharedMemorySize, SMEM_BYTES);

    dim3 grid(WDIM / TN, HDIM / TM, 2 * COUT);   // (4, 8, 64) -> 2048 CTAs
    dyn_conv_hmma<<<grid, NTHR, SMEM_BYTES>>>(x, Wp, bp, out);
}

// round 9
// speedup vs baseline: 2.2616x; 1.0764x over previous
#include <cuda_runtime.h>
#include <cstdint>

#define CIN   32
#define COUT  32
#define HDIM  64
#define WDIM  64
#define TM    8       // tile rows (y)
#define TN    16      // tile cols (x)
#define NTHR  256
#define XST   40      // xs channel-dim stride (words)

// smem byte offsets
#define OFF_A    0               // 32 blk * 512B  = 16384   (A tf32 fragments)
#define OFF_B    16384           // 72 blk * 512B  = 36864   (B tf32 fragments)
#define OFF_XS   53248           // 10*18*40*4     = 28800   (pixel-major halo, fp32)
#define OFF_BPS  82048           // 288 * 4        = 1152
#define OFF_WPB  83200           // 32 * 4         = 128
#define SMEM_BYTES 83328

typedef unsigned int u32;

__device__ __forceinline__ u32 f2tf(float v) {
    u32 r;
    asm("cvt.rna.tf32.f32 %0, %1;" : "=r"(r) : "f"(v));
    return r;
}
__device__ __forceinline__ void mma1688(float* d, const uint4& a, u32 b0, u32 b1) {
    asm volatile(
        "mma.sync.aligned.m16n8k8.row.col.f32.tf32.tf32.f32 "
        "{%0,%1,%2,%3}, {%4,%5,%6,%7}, {%8,%9}, {%0,%1,%2,%3};"
        : "+f"(d[0]), "+f"(d[1]), "+f"(d[2]), "+f"(d[3])
        : "r"(a.x), "r"(a.y), "r"(a.z), "r"(a.w), "r"(b0), "r"(b1));
}

__global__ __launch_bounds__(NTHR, 2)
void dyn_conv_tf32(const float* __restrict__ x,
                   const float* __restrict__ Wp,
                   const float* __restrict__ bp,
                   float* __restrict__ out)
{
    extern __shared__ char sm[];
    u32*   Afw = (u32*)(sm + OFF_A);
    u32*   Bfw = (u32*)(sm + OFF_B);
    float* xs  = (float*)(sm + OFF_XS);
    float* bps = (float*)(sm + OFF_BPS);
    float* wpb = (float*)(sm + OFF_WPB);

    const int bz = blockIdx.z;
    const int b  = bz >> 5;
    const int o  = bz & 31;
    const int x0 = blockIdx.x * TN;
    const int y0 = blockIdx.y * TM;
    const int tid  = threadIdx.x;
    const int lane = tid & 31;
    const int g = lane >> 2;
    const int q = lane & 3;
    const int mt = tid >> 5;       // warp = m-tile (pixel row y0+mt, 16 x-cols)
    const float bpo = bp[9216 + o];

    // ================= Staging =================
    // B tf32 fragments: blk = (kk*4+oc)*2+part, word = lane*4 + s
    //   value(kk,oc,part,lane(g,q),s): ks=part*2+(s>>1), breg=s&1
    //   = Wp[o*288 + (8oc+g)*9 + kk][8ks + q + 4*breg]
    {
        const float* wpo = Wp + (size_t)o * 9216;
        #pragma unroll 4
        for (u32 i = tid; i < 9216; i += NTHR) {
            u32 n = i >> 5, cp = i & 31;
            u32 c = n / 9u, kk = n - 9u * c;
            u32 tf = f2tf(wpo[i]);                       // coalesced LDG
            u32 oc = c >> 3, gg = c & 7;
            u32 qq = cp & 3, breg = (cp >> 2) & 1, ks = cp >> 3;
            u32 part = ks >> 1, s = (ks & 1) * 2 + breg;
            Bfw[((kk * 4 + oc) * 2 + part) * 128 + (4 * gg + qq) * 4 + s] = tf;
        }
    }
    // A tf32 fragments: blk = mt*4+ks, word = lane*4 + r
    //   r = rowhalf + 2*colhalf: value = x[pixel tx = g + 8*rowhalf][cp = 8ks + q + 4*colhalf]
    {
        const float* xb = x + (size_t)b * CIN * HDIM * WDIM;
        #pragma unroll 4
        for (u32 i = tid; i < 4096; i += NTHR) {
            u32 cp = i >> 7, m = i & 127;
            u32 yy = y0 + (m >> 4), xx = x0 + (m & 15);
            u32 tf = f2tf(xb[cp * 4096 + yy * WDIM + xx]);   // coalesced-ish LDG
            u32 mtt = m >> 4, tx = m & 15;
            u32 gg = tx & 7, rh = tx >> 3;
            u32 qq = cp & 3, ks = cp >> 3, ch = (cp >> 2) & 1;
            Afw[(mtt * 4 + ks) * 128 + (4 * gg + qq) * 4 + rh + 2 * ch] = tf;
        }
    }
    // xs halo fp32, pixel-major: word = (row*18+col)*40 + c
    {
        const float* xb = x + (size_t)b * CIN * HDIM * WDIM;
        #pragma unroll 4
        for (u32 i = tid; i < 5760; i += NTHR) {
            u32 c = i / 180u, j = i - 180u * c;
            u32 r = j / 18u, col = j - 18u * r;
            float v = 0.0f;
            int yy = (int)(y0 + r) - 1, xx = (int)(x0 + col) - 1;
            if (yy >= 0 && yy < HDIM && xx >= 0 && xx < WDIM)
                v = xb[(c * HDIM + yy) * WDIM + xx];
            xs[(r * 18 + col) * XST + c] = v;
        }
    }
    for (u32 i = tid; i < 288; i += NTHR) {       // predictor bias, permuted [kk*32+c]
        u32 c = i / 9u, kk = i - 9u * c;
        bps[kk * 32 + c] = bp[o * 288 + i];
    }
    if (tid < 32) wpb[tid] = Wp[(size_t)(9216 + o) * 32 + tid];
    __syncthreads();

    // ================= A fragments (persistent, 16 regs) =================
    uint4 af[4];
    {
        const uint4* Aq = (const uint4*)(sm + OFF_A);
        #pragma unroll
        for (int ks = 0; ks < 4; ks++)
            af[ks] = Aq[(mt * 4 + ks) * 32 + lane];
    }

    // ================= Fused single pass over kk =================
    const uint4* Bq = (const uint4*)(sm + OFF_B);
    const int txr0 = g, txr1 = g + 8;
    float s2[2][8], tp[2][8];
    #pragma unroll
    for (int r = 0; r < 2; r++)
        #pragma unroll
        for (int cl = 0; cl < 8; cl++) { s2[r][cl] = 0.0f; tp[r][cl] = 0.0f; }

    #pragma unroll
    for (int kk = 0; kk < 9; kk++) {
        const int dy = kk / 3, dx = kk - 3 * (kk / 3);

        // accs initialized with predictor bias (broadcast LDS.64)
        float accT[4][4];
        #pragma unroll
        for (int oc = 0; oc < 4; oc++) {
            float2 bv = *(const float2*)&bps[32 * kk + 8 * oc + 2 * q];
            accT[oc][0] = bv.x; accT[oc][1] = bv.y;
            accT[oc][2] = bv.x; accT[oc][3] = bv.y;
        }
        // 4 independent c-octet tiles, K=32 in 4 tf32 k-steps
        #pragma unroll
        for (int oc = 0; oc < 4; oc++) {
            uint4 p0 = Bq[((kk * 4 + oc) * 2 + 0) * 32 + lane];   // LDS.128
            uint4 p1 = Bq[((kk * 4 + oc) * 2 + 1) * 32 + lane];
            mma1688(accT[oc], af[0], p0.x, p0.y);
            mma1688(accT[oc], af[1], p0.z, p0.w);
            mma1688(accT[oc], af[2], p1.x, p1.y);
            mma1688(accT[oc], af[3], p1.z, p1.w);
        }
        // c-norm: per-thread partials + quad reduce (all 32 c live in-warp)
        float s1r0 = 0.0f, s1r1 = 0.0f;
        #pragma unroll
        for (int oc = 0; oc < 4; oc++) {
            s1r0 = fmaf(accT[oc][0], accT[oc][0], s1r0);
            s1r0 = fmaf(accT[oc][1], accT[oc][1], s1r0);
            s1r1 = fmaf(accT[oc][2], accT[oc][2], s1r1);
            s1r1 = fmaf(accT[oc][3], accT[oc][3], s1r1);
        }
        s1r0 += __shfl_xor_sync(0xffffffffu, s1r0, 1);
        s1r0 += __shfl_xor_sync(0xffffffffu, s1r0, 2);
        s1r1 += __shfl_xor_sync(0xffffffffu, s1r1, 1);
        s1r1 += __shfl_xor_sync(0xffffffffu, s1r1, 2);
        float inv1r0 = rsqrtf(fmaxf(s1r0, 1e-24f));   // == 1/max(sqrt,1e-12)
        float inv1r1 = rsqrtf(fmaxf(s1r1, 1e-24f));

        // scale by inv1; accumulate s2[c] and patch contraction (LDS.64 pv pairs)
        #pragma unroll
        for (int oc = 0; oc < 4; oc++) {
            float2 pv0 = *(const float2*)&xs[((mt + dy) * 18 + txr0 + dx) * XST + 8 * oc + 2 * q];
            float2 pv1 = *(const float2*)&xs[((mt + dy) * 18 + txr1 + dx) * XST + 8 * oc + 2 * q];
            float d00 = accT[oc][0] * inv1r0;
            float d01 = accT[oc][1] * inv1r0;
            float d10 = accT[oc][2] * inv1r1;
            float d11 = accT[oc][3] * inv1r1;
            s2[0][2 * oc]     = fmaf(d00, d00, s2[0][2 * oc]);
            s2[0][2 * oc + 1] = fmaf(d01, d01, s2[0][2 * oc + 1]);
            s2[1][2 * oc]     = fmaf(d10, d10, s2[1][2 * oc]);
            s2[1][2 * oc + 1] = fmaf(d11, d11, s2[1][2 * oc + 1]);
            tp[0][2 * oc]     = fmaf(d00, pv0.x, tp[0][2 * oc]);
            tp[0][2 * oc + 1] = fmaf(d01, pv0.y, tp[0][2 * oc + 1]);
            tp[1][2 * oc]     = fmaf(d10, pv1.x, tp[1][2 * oc]);
            tp[1][2 * oc + 1] = fmaf(d11, pv1.y, tp[1][2 * oc + 1]);
        }
    }

    // ================= k-norm + dynamic bias + output =================
    float op0 = 0.0f, op1 = 0.0f;
    #pragma unroll
    for (int oc = 0; oc < 4; oc++) {
        float2 wv  = *(const float2*)&wpb[8 * oc + 2 * q];
        float2 xc0 = *(const float2*)&xs[((mt + 1) * 18 + txr0 + 1) * XST + 8 * oc + 2 * q];
        float2 xc1 = *(const float2*)&xs[((mt + 1) * 18 + txr1 + 1) * XST + 8 * oc + 2 * q];
        op0 = fmaf(tp[0][2 * oc],     rsqrtf(fmaxf(s2[0][2 * oc],     1e-24f)), op0);
        op0 = fmaf(tp[0][2 * oc + 1], rsqrtf(fmaxf(s2[0][2 * oc + 1], 1e-24f)), op0);
        op1 = fmaf(tp[1][2 * oc],     rsqrtf(fmaxf(s2[1][2 * oc],     1e-24f)), op1);
        op1 = fmaf(tp[1][2 * oc + 1], rsqrtf(fmaxf(s2[1][2 * oc + 1], 1e-24f)), op1);
        op0 = fmaf(wv.x, xc0.x, op0);
        op0 = fmaf(wv.y, xc0.y, op0);
        op1 = fmaf(wv.x, xc1.x, op1);
        op1 = fmaf(wv.y, xc1.y, op1);
    }
    op0 += __shfl_xor_sync(0xffffffffu, op0, 1);
    op0 += __shfl_xor_sync(0xffffffffu, op0, 2);
    op1 += __shfl_xor_sync(0xffffffffu, op1, 1);
    op1 += __shfl_xor_sync(0xffffffffu, op1, 2);

    if (q == 0) {
        float* orow = out + (((size_t)b * COUT + o) * HDIM + (y0 + mt)) * WDIM + x0;
        orow[txr0] = op0 + bpo;
        orow[txr1] = op1 + bpo;
    }
}

extern "C" void kernel_launch(void* const* d_in, const int* in_sizes, int n_in,
                              void* d_out, int out_size)
{
    const float* x  = (const float*)d_in[0];   // (2, 32, 64, 64)
    const float* Wp = (const float*)d_in[1];   // (9248, 32)
    const float* bp = (const float*)d_in[2];   // (9248,)
    float* out = (float*)d_out;                // (2, 32, 64, 64)

    cudaFuncSetAttribute(dyn_conv_tf32,
                         cudaFuncAttributeMaxDynamicSharedMemorySize, SMEM_BYTES);

    dim3 grid(WDIM / TN, HDIM / TM, 2 * COUT);   // (4, 8, 64) -> 2048 CTAs
    dyn_conv_tf32<<<grid, NTHR, SMEM_BYTES>>>(x, Wp, bp, out);
}

// round 11
// speedup vs baseline: 3.3383x; 1.4761x over previous
#include <cuda_runtime.h>
#include <cstdint>

#define CIN   32
#define COUT  32
#define HDIM  64
#define WDIM  64
#define TM    8       // tile rows (y)
#define TN    16      // tile cols (x)
#define NTHR  256
#define XST   40      // xs channel-dim stride (words)

// main-kernel smem byte offsets
#define OFF_B    0               // 72 blk * 512B  = 36864   (B tf32 fragments)
#define OFF_XS   36864           // 10*18*40*4     = 28800   (pixel-major halo, fp32)
#define OFF_BPS  65664           // 288 * 4        = 1152
#define OFF_WPB  66816           // 32 * 4         = 128
#define SMEM_BYTES 66944

typedef unsigned int u32;

// ---- device scratch (precomputed layouts) ----
__device__ u32   BGg[32 * 9216];          // B fragments per o
__device__ float BPSg[32 * 288];          // permuted predictor bias per o
__device__ u32   AGg[2 * 32 * 4096];      // A fragments per (b, tile)
__device__ float XPg[2 * 4356 * 32];      // padded x, pixel-major: [b][yy*66+xx][c]

__device__ __forceinline__ u32 f2tf(float v) {
    u32 r;
    asm("cvt.rna.tf32.f32 %0, %1;" : "=r"(r) : "f"(v));
    return r;
}
__device__ __forceinline__ void mma1688(float* d, const uint4& a, u32 b0, u32 b1) {
    asm volatile(
        "mma.sync.aligned.m16n8k8.row.col.f32.tf32.tf32.f32 "
        "{%0,%1,%2,%3}, {%4,%5,%6,%7}, {%8,%9}, {%0,%1,%2,%3};"
        : "+f"(d[0]), "+f"(d[1]), "+f"(d[2]), "+f"(d[3])
        : "r"(a.x), "r"(a.y), "r"(a.z), "r"(a.w), "r"(b0), "r"(b1));
}

// ================= Pre-pass: build all fragment layouts =================
__global__ void prepass(const float* __restrict__ x,
                        const float* __restrict__ Wp,
                        const float* __restrict__ bp)
{
    const u32 t0 = blockIdx.x * blockDim.x + threadIdx.x;
    const u32 stride = gridDim.x * blockDim.x;

    // B fragments: 32 o * 9216
    for (u32 idx = t0; idx < 32u * 9216u; idx += stride) {
        u32 o = idx / 9216u, i = idx - o * 9216u;
        u32 n = i >> 5, cp = i & 31;
        u32 c = n / 9u, kk = n - 9u * c;
        u32 oc = c >> 3, gg = c & 7;
        u32 qq = cp & 3, breg = (cp >> 2) & 1, ks = cp >> 3;
        u32 part = ks >> 1, s = (ks & 1) * 2 + breg;
        BGg[o * 9216 + ((kk * 4 + oc) * 2 + part) * 128 + (4 * gg + qq) * 4 + s]
            = f2tf(Wp[(size_t)o * 9216 + i]);
    }
    // permuted bias: 32 o * 288
    for (u32 idx = t0; idx < 32u * 288u; idx += stride) {
        u32 o = idx / 288u, j = idx - o * 288u;
        u32 c = j / 9u, kk = j - 9u * c;
        BPSg[o * 288 + kk * 32 + c] = bp[o * 288 + j];
    }
    // A fragments: 2 b * 32 tiles * 4096
    for (u32 idx = t0; idx < 2u * 32u * 4096u; idx += stride) {
        u32 b = idx >> 17;
        u32 rest = idx & 131071u;
        u32 cp = rest >> 12;
        u32 mg = rest & 4095u;              // global pixel
        u32 y = mg >> 6, xx = mg & 63;
        u32 tile = (y >> 3) * 4 + (xx >> 4);
        u32 mtt = y & 7, tx = xx & 15;
        u32 gg = tx & 7, rh = tx >> 3;
        u32 qq = cp & 3, ks = cp >> 3, ch = (cp >> 2) & 1;
        u32 tf = f2tf(x[((size_t)(b * 32 + cp) * HDIM + y) * WDIM + xx]);
        AGg[(b * 32 + tile) * 4096 + (mtt * 4 + ks) * 128 + (4 * gg + qq) * 4 + rh + 2 * ch] = tf;
    }
    // padded pixel-major x: 2 b * 66*66 * 32
    for (u32 idx = t0; idx < 2u * 4356u * 32u; idx += stride) {
        u32 b = idx / 139392u;
        u32 rest = idx - b * 139392u;
        u32 pos = rest >> 5, c = rest & 31;
        u32 yy = pos / 66u, xxp = pos - 66u * yy;
        float v = 0.0f;
        if (yy >= 1 && yy <= 64 && xxp >= 1 && xxp <= 64)
            v = x[((size_t)(b * 32 + c) * HDIM + (yy - 1)) * WDIM + (xxp - 1)];
        XPg[(size_t)b * 139392u + pos * 32 + c] = v;
    }
}

// ================= Main kernel =================
__global__ __launch_bounds__(NTHR, 2)
void dyn_conv_tf32(const float* __restrict__ x,
                   const float* __restrict__ Wp,
                   const float* __restrict__ bp,
                   float* __restrict__ out)
{
    extern __shared__ char sm[];
    float* xs  = (float*)(sm + OFF_XS);
    float* bps = (float*)(sm + OFF_BPS);
    float* wpb = (float*)(sm + OFF_WPB);

    const int bz = blockIdx.z;
    const int b  = bz >> 5;
    const int o  = bz & 31;
    const int x0 = blockIdx.x * TN;
    const int y0 = blockIdx.y * TM;
    const int tid  = threadIdx.x;
    const int lane = tid & 31;
    const int g = lane >> 2;
    const int q = lane & 3;
    const int mt = tid >> 5;       // warp = m-tile (pixel row y0+mt, 16 x-cols)
    const float bpo = bp[9216 + o];

    // ---- A fragments: direct coalesced LDG.128 into regs ----
    uint4 af[4];
    {
        const uint4* Aq = (const uint4*)AGg
            + (size_t)(b * 32 + blockIdx.y * 4 + blockIdx.x) * 1024;
        #pragma unroll
        for (int ks = 0; ks < 4; ks++)
            af[ks] = Aq[(mt * 4 + ks) * 32 + lane];
    }

    // ---- B fragments: pure copy global->smem (LDG.128 / STS.128) ----
    {
        uint4* Bs4 = (uint4*)(sm + OFF_B);
        const uint4* Bg4 = (const uint4*)BGg + (size_t)o * 2304;
        #pragma unroll
        for (int j = 0; j < 9; j++)
            Bs4[tid + j * NTHR] = Bg4[tid + j * NTHR];
    }
    // ---- xs halo: float4 copies from padded pixel-major image ----
    {
        float4* xs4 = (float4*)xs;
        const float4* xp4 = (const float4*)XPg + (size_t)b * 34848;
        #pragma unroll
        for (int j = 0; j < 6; j++) {
            u32 i = tid + j * NTHR;           // 0..1535; need 1440
            if (i < 1440) {
                u32 pos = i >> 3, c4 = i & 7;
                u32 r = pos / 18u, col = pos - 18u * r;
                xs4[pos * 10 + c4] = xp4[((y0 + r) * 66 + x0 + col) * 8 + c4];
            }
        }
    }
    // ---- bias + wpb copies (full coverage) ----
    for (int i = tid; i < 288; i += NTHR) bps[i] = BPSg[o * 288 + i];
    if (tid < 32) wpb[tid] = Wp[(size_t)(9216 + o) * 32 + tid];
    __syncthreads();

    // ================= Fused single pass over kk =================
    const uint4* Bq = (const uint4*)(sm + OFF_B);
    const int txr0 = g, txr1 = g + 8;
    float s2[2][8], tp[2][8];
    #pragma unroll
    for (int r = 0; r < 2; r++)
        #pragma unroll
        for (int cl = 0; cl < 8; cl++) { s2[r][cl] = 0.0f; tp[r][cl] = 0.0f; }

    #pragma unroll
    for (int kk = 0; kk < 9; kk++) {
        const int dy = kk / 3, dx = kk - 3 * (kk / 3);

        // accs initialized with predictor bias (broadcast LDS.64)
        float accT[4][4];
        #pragma unroll
        for (int oc = 0; oc < 4; oc++) {
            float2 bv = *(const float2*)&bps[32 * kk + 8 * oc + 2 * q];
            accT[oc][0] = bv.x; accT[oc][1] = bv.y;
            accT[oc][2] = bv.x; accT[oc][3] = bv.y;
        }
        // 4 independent c-octet tiles, K=32 in 4 tf32 k-steps
        #pragma unroll
        for (int oc = 0; oc < 4; oc++) {
            uint4 p0 = Bq[((kk * 4 + oc) * 2 + 0) * 32 + lane];   // LDS.128
            uint4 p1 = Bq[((kk * 4 + oc) * 2 + 1) * 32 + lane];
            mma1688(accT[oc], af[0], p0.x, p0.y);
            mma1688(accT[oc], af[1], p0.z, p0.w);
            mma1688(accT[oc], af[2], p1.x, p1.y);
            mma1688(accT[oc], af[3], p1.z, p1.w);
        }
        // c-norm: per-thread partials + quad reduce (all 32 c live in-warp)
        float s1r0 = 0.0f, s1r1 = 0.0f;
        #pragma unroll
        for (int oc = 0; oc < 4; oc++) {
            s1r0 = fmaf(accT[oc][0], accT[oc][0], s1r0);
            s1r0 = fmaf(accT[oc][1], accT[oc][1], s1r0);
            s1r1 = fmaf(accT[oc][2], accT[oc][2], s1r1);
            s1r1 = fmaf(accT[oc][3], accT[oc][3], s1r1);
        }
        s1r0 += __shfl_xor_sync(0xffffffffu, s1r0, 1);
        s1r0 += __shfl_xor_sync(0xffffffffu, s1r0, 2);
        s1r1 += __shfl_xor_sync(0xffffffffu, s1r1, 1);
        s1r1 += __shfl_xor_sync(0xffffffffu, s1r1, 2);
        float inv1r0 = rsqrtf(fmaxf(s1r0, 1e-24f));   // == 1/max(sqrt,1e-12)
        float inv1r1 = rsqrtf(fmaxf(s1r1, 1e-24f));

        // scale by inv1; accumulate s2[c] and patch contraction (LDS.64 pv pairs)
        #pragma unroll
        for (int oc = 0; oc < 4; oc++) {
            float2 pv0 = *(const float2*)&xs[((mt + dy) * 18 + txr0 + dx) * XST + 8 * oc + 2 * q];
            float2 pv1 = *(const float2*)&xs[((mt + dy) * 18 + txr1 + dx) * XST + 8 * oc + 2 * q];
            float d00 = accT[oc][0] * inv1r0;
            float d01 = accT[oc][1] * inv1r0;
            float d10 = accT[oc][2] * inv1r1;
            float d11 = accT[oc][3] * inv1r1;
            s2[0][2 * oc]     = fmaf(d00, d00, s2[0][2 * oc]);
            s2[0][2 * oc + 1] = fmaf(d01, d01, s2[0][2 * oc + 1]);
            s2[1][2 * oc]     = fmaf(d10, d10, s2[1][2 * oc]);
            s2[1][2 * oc + 1] = fmaf(d11, d11, s2[1][2 * oc + 1]);
            tp[0][2 * oc]     = fmaf(d00, pv0.x, tp[0][2 * oc]);
            tp[0][2 * oc + 1] = fmaf(d01, pv0.y, tp[0][2 * oc + 1]);
            tp[1][2 * oc]     = fmaf(d10, pv1.x, tp[1][2 * oc]);
            tp[1][2 * oc + 1] = fmaf(d11, pv1.y, tp[1][2 * oc + 1]);
        }
    }

    // ================= k-norm + dynamic bias + output =================
    float op0 = 0.0f, op1 = 0.0f;
    #pragma unroll
    for (int oc = 0; oc < 4; oc++) {
        float2 wv  = *(const float2*)&wpb[8 * oc + 2 * q];
        float2 xc0 = *(const float2*)&xs[((mt + 1) * 18 + txr0 + 1) * XST + 8 * oc + 2 * q];
        float2 xc1 = *(const float2*)&xs[((mt + 1) * 18 + txr1 + 1) * XST + 8 * oc + 2 * q];
        op0 = fmaf(tp[0][2 * oc],     rsqrtf(fmaxf(s2[0][2 * oc],     1e-24f)), op0);
        op0 = fmaf(tp[0][2 * oc + 1], rsqrtf(fmaxf(s2[0][2 * oc + 1], 1e-24f)), op0);
        op1 = fmaf(tp[1][2 * oc],     rsqrtf(fmaxf(s2[1][2 * oc],     1e-24f)), op1);
        op1 = fmaf(tp[1][2 * oc + 1], rsqrtf(fmaxf(s2[1][2 * oc + 1], 1e-24f)), op1);
        op0 = fmaf(wv.x, xc0.x, op0);
        op0 = fmaf(wv.y, xc0.y, op0);
        op1 = fmaf(wv.x, xc1.x, op1);
        op1 = fmaf(wv.y, xc1.y, op1);
    }
    op0 += __shfl_xor_sync(0xffffffffu, op0, 1);
    op0 += __shfl_xor_sync(0xffffffffu, op0, 2);
    op1 += __shfl_xor_sync(0xffffffffu, op1, 1);
    op1 += __shfl_xor_sync(0xffffffffu, op1, 2);

    if (q == 0) {
        float* orow = out + (((size_t)b * COUT + o) * HDIM + (y0 + mt)) * WDIM + x0;
        orow[txr0] = op0 + bpo;
        orow[txr1] = op1 + bpo;
    }
}

extern "C" void kernel_launch(void* const* d_in, const int* in_sizes, int n_in,
                              void* d_out, int out_size)
{
    const float* x  = (const float*)d_in[0];   // (2, 32, 64, 64)
    const float* Wp = (const float*)d_in[1];   // (9248, 32)
    const float* bp = (const float*)d_in[2];   // (9248,)
    float* out = (float*)d_out;                // (2, 32, 64, 64)

    cudaFuncSetAttribute(dyn_conv_tf32,
                         cudaFuncAttributeMaxDynamicSharedMemorySize, SMEM_BYTES);

    prepass<<<256, 256>>>(x, Wp, bp);

    dim3 grid(WDIM / TN, HDIM / TM, 2 * COUT);   // (4, 8, 64) -> 2048 CTAs
    dyn_conv_tf32<<<grid, NTHR, SMEM_BYTES>>>(x, Wp, bp, out);
}

// round 12
// speedup vs baseline: 4.1980x; 1.2575x over previous
#include <cuda_runtime.h>
#include <cuda_fp16.h>
#include <cstdint>

#define CIN   32
#define COUT  32
#define HDIM  64
#define WDIM  64
#define TM    8       // tile rows (y)
#define TN    16      // tile cols (x)
#define NTHR  256
#define XST   40      // xs channel-dim stride (words)

// main-kernel smem byte offsets
#define OFF_B    0               // 36 blk * 512B  = 18432   (B f16 fragments)
#define OFF_XS   18432           // 10*18*40*4     = 28800   (pixel-major halo, fp32)
#define OFF_BPS  47232           // 288 * 4        = 1152
#define OFF_WPB  48384           // 32 * 4         = 128
#define SMEM_BYTES 48512

typedef unsigned int u32;

// ---- device scratch (precomputed layouts) ----
__device__ u32   BGg[32 * 4608];          // B f16 fragments per o (36 blk * 128 u32)
__device__ float BPSg[32 * 288];          // permuted predictor bias per o
__device__ u32   AGg[2 * 32 * 2048];      // A f16 fragments per (b, tile) (16 blk * 128 u32)
__device__ float XPg[2 * 4356 * 32];      // padded x, pixel-major: [b][yy*66+xx][c]

__device__ __forceinline__ u32 pkh2(float a, float b) {
    __half2 h = __floats2half2_rn(a, b);
    return *(u32*)&h;
}
__device__ __forceinline__ void mmaf16(float* d, const uint4& a, u32 b0, u32 b1) {
    asm volatile(
        "mma.sync.aligned.m16n8k16.row.col.f32.f16.f16.f32 "
        "{%0,%1,%2,%3}, {%4,%5,%6,%7}, {%8,%9}, {%0,%1,%2,%3};"
        : "+f"(d[0]), "+f"(d[1]), "+f"(d[2]), "+f"(d[3])
        : "r"(a.x), "r"(a.y), "r"(a.z), "r"(a.w), "r"(b0), "r"(b1));
}

// ================= Pre-pass: build all fragment layouts =================
__global__ void prepass(const float* __restrict__ x,
                        const float* __restrict__ Wp,
                        const float* __restrict__ bp)
{
    const u32 t0 = blockIdx.x * blockDim.x + threadIdx.x;
    const u32 stride = gridDim.x * blockDim.x;

    // B f16 fragments: 32 o * 36 blk(kk*4+oc) * 128 u32 (lane*4 + s)
    //   s: ks = s>>1, r = s&1;  value = half2{ W[c][cp], W[c][cp+1] }
    //   c = 8*oc + g, cp = 16*ks + 2*q + 8*r;  W[c][cp] = Wp[(o*288 + c*9 + kk)*32 + cp]
    for (u32 idx = t0; idx < 32u * 4608u; idx += stride) {
        u32 o = idx / 4608u, i = idx - o * 4608u;
        u32 blk = i >> 7, w = i & 127u;
        u32 lane = w >> 2, s = w & 3u;
        u32 g = lane >> 2, q = lane & 3u;
        u32 kk = blk >> 2, oc = blk & 3u;
        u32 ks = s >> 1, r = s & 1u;
        u32 c = 8u * oc + g, cp = 16u * ks + 2u * q + 8u * r;
        const float* row = Wp + ((size_t)o * 288u + c * 9u + kk) * 32u + cp;
        BGg[idx] = pkh2(row[0], row[1]);
    }
    // permuted bias: 32 o * 288
    for (u32 idx = t0; idx < 32u * 288u; idx += stride) {
        u32 o = idx / 288u, j = idx - o * 288u;
        u32 c = j / 9u, kk = j - 9u * c;
        BPSg[o * 288 + kk * 32 + c] = bp[o * 288 + j];
    }
    // A f16 fragments: 2 b * 32 tiles * 16 blk(mtt*2+ks) * 128 u32 (lane*4 + s)
    //   s: px = g + 8*(s&1), cp = 16*ks + 2*q + 8*(s>>1); value = half2{x[cp], x[cp+1]}
    for (u32 idx = t0; idx < 2u * 32u * 2048u; idx += stride) {
        u32 b = idx >> 16;
        u32 i = idx & 65535u;
        u32 tile = i >> 11, j = i & 2047u;
        u32 blk = j >> 7, w = j & 127u;
        u32 lane = w >> 2, s = w & 3u;
        u32 g = lane >> 2, q = lane & 3u;
        u32 mtt = blk >> 1, ks = blk & 1u;
        u32 tiley = tile >> 2, tilex = tile & 3u;
        u32 y = tiley * 8u + mtt;
        u32 xx = tilex * 16u + g + 8u * (s & 1u);
        u32 cp = 16u * ks + 2u * q + 8u * (s >> 1);
        float v0 = x[((size_t)(b * 32 + cp) * HDIM + y) * WDIM + xx];
        float v1 = x[((size_t)(b * 32 + cp + 1) * HDIM + y) * WDIM + xx];
        AGg[idx] = pkh2(v0, v1);
    }
    // padded pixel-major x: 2 b * 66*66 * 32
    for (u32 idx = t0; idx < 2u * 4356u * 32u; idx += stride) {
        u32 b = idx / 139392u;
        u32 rest = idx - b * 139392u;
        u32 pos = rest >> 5, c = rest & 31u;
        u32 yy = pos / 66u, xxp = pos - 66u * yy;
        float v = 0.0f;
        if (yy >= 1 && yy <= 64 && xxp >= 1 && xxp <= 64)
            v = x[((size_t)(b * 32 + c) * HDIM + (yy - 1)) * WDIM + (xxp - 1)];
        XPg[(size_t)b * 139392u + pos * 32 + c] = v;
    }
}

// ================= Main kernel =================
__global__ __launch_bounds__(NTHR, 2)
void dyn_conv_f16(const float* __restrict__ x,
                  const float* __restrict__ Wp,
                  const float* __restrict__ bp,
                  float* __restrict__ out)
{
    extern __shared__ char sm[];
    float* xs  = (float*)(sm + OFF_XS);
    float* bps = (float*)(sm + OFF_BPS);
    float* wpb = (float*)(sm + OFF_WPB);

    const int bz = blockIdx.z;
    const int b  = bz >> 5;
    const int o  = bz & 31;
    const int x0 = blockIdx.x * TN;
    const int y0 = blockIdx.y * TM;
    const int tid  = threadIdx.x;
    const int lane = tid & 31;
    const int g = lane >> 2;
    const int q = lane & 3;
    const int mt = tid >> 5;       // warp = m-tile (pixel row y0+mt, 16 x-cols)
    const float bpo = bp[9216 + o];

    // ---- A fragments: 2 direct coalesced LDG.128 ----
    uint4 af[2];
    {
        const uint4* Aq = (const uint4*)AGg
            + (size_t)(b * 32 + blockIdx.y * 4 + blockIdx.x) * 512;
        #pragma unroll
        for (int ks = 0; ks < 2; ks++)
            af[ks] = Aq[(mt * 2 + ks) * 32 + lane];
    }

    // ---- B fragments: pure copy global->smem (1152 uint4) ----
    {
        uint4* Bs4 = (uint4*)(sm + OFF_B);
        const uint4* Bg4 = (const uint4*)BGg + (size_t)o * 1152;
        #pragma unroll
        for (int j = 0; j < 5; j++) {
            int i = tid + j * NTHR;
            if (i < 1152) Bs4[i] = Bg4[i];
        }
    }
    // ---- xs halo: float4 copies from padded pixel-major image ----
    {
        float4* xs4 = (float4*)xs;
        const float4* xp4 = (const float4*)XPg + (size_t)b * 34848;
        #pragma unroll
        for (int j = 0; j < 6; j++) {
            u32 i = tid + j * NTHR;           // need 1440
            if (i < 1440) {
                u32 pos = i >> 3, c4 = i & 7;
                u32 r = pos / 18u, col = pos - 18u * r;
                xs4[pos * 10 + c4] = xp4[((y0 + r) * 66 + x0 + col) * 8 + c4];
            }
        }
    }
    // ---- bias + wpb copies ----
    for (int i = tid; i < 288; i += NTHR) bps[i] = BPSg[o * 288 + i];
    if (tid < 32) wpb[tid] = Wp[(size_t)(9216 + o) * 32 + tid];
    __syncthreads();

    // ================= Fused single pass over kk =================
    const uint4* Bq = (const uint4*)(sm + OFF_B);
    const int txr0 = g, txr1 = g + 8;
    float s2[2][8], tp[2][8];
    #pragma unroll
    for (int r = 0; r < 2; r++)
        #pragma unroll
        for (int cl = 0; cl < 8; cl++) { s2[r][cl] = 0.0f; tp[r][cl] = 0.0f; }

    #pragma unroll
    for (int kk = 0; kk < 9; kk++) {
        const int dy = kk / 3, dx = kk - 3 * (kk / 3);

        // accs initialized with predictor bias (broadcast LDS.64)
        float accT[4][4];
        #pragma unroll
        for (int oc = 0; oc < 4; oc++) {
            float2 bv = *(const float2*)&bps[32 * kk + 8 * oc + 2 * q];
            accT[oc][0] = bv.x; accT[oc][1] = bv.y;
            accT[oc][2] = bv.x; accT[oc][3] = bv.y;
        }
        // 4 independent c-octet tiles, K=32 in 2 f16 k-steps; 1 LDS.128 per (kk,oc)
        #pragma unroll
        for (int oc = 0; oc < 4; oc++) {
            uint4 bb = Bq[(kk * 4 + oc) * 32 + lane];
            mmaf16(accT[oc], af[0], bb.x, bb.y);   // cp 0..15
            mmaf16(accT[oc], af[1], bb.z, bb.w);   // cp 16..31
        }
        // c-norm: per-thread partials + quad reduce (all 32 c live in-warp)
        float s1r0 = 0.0f, s1r1 = 0.0f;
        #pragma unroll
        for (int oc = 0; oc < 4; oc++) {
            s1r0 = fmaf(accT[oc][0], accT[oc][0], s1r0);
            s1r0 = fmaf(accT[oc][1], accT[oc][1], s1r0);
            s1r1 = fmaf(accT[oc][2], accT[oc][2], s1r1);
            s1r1 = fmaf(accT[oc][3], accT[oc][3], s1r1);
        }
        s1r0 += __shfl_xor_sync(0xffffffffu, s1r0, 1);
        s1r0 += __shfl_xor_sync(0xffffffffu, s1r0, 2);
        s1r1 += __shfl_xor_sync(0xffffffffu, s1r1, 1);
        s1r1 += __shfl_xor_sync(0xffffffffu, s1r1, 2);
        float inv1r0 = rsqrtf(fmaxf(s1r0, 1e-24f));   // == 1/max(sqrt,1e-12)
        float inv1r1 = rsqrtf(fmaxf(s1r1, 1e-24f));

        // scale by inv1; accumulate s2[c] and patch contraction (LDS.64 pv pairs)
        #pragma unroll
        for (int oc = 0; oc < 4; oc++) {
            float2 pv0 = *(const float2*)&xs[((mt + dy) * 18 + txr0 + dx) * XST + 8 * oc + 2 * q];
            float2 pv1 = *(const float2*)&xs[((mt + dy) * 18 + txr1 + dx) * XST + 8 * oc + 2 * q];
            float d00 = accT[oc][0] * inv1r0;
            float d01 = accT[oc][1] * inv1r0;
            float d10 = accT[oc][2] * inv1r1;
            float d11 = accT[oc][3] * inv1r1;
            s2[0][2 * oc]     = fmaf(d00, d00, s2[0][2 * oc]);
            s2[0][2 * oc + 1] = fmaf(d01, d01, s2[0][2 * oc + 1]);
            s2[1][2 * oc]     = fmaf(d10, d10, s2[1][2 * oc]);
            s2[1][2 * oc + 1] = fmaf(d11, d11, s2[1][2 * oc + 1]);
            tp[0][2 * oc]     = fmaf(d00, pv0.x, tp[0][2 * oc]);
            tp[0][2 * oc + 1] = fmaf(d01, pv0.y, tp[0][2 * oc + 1]);
            tp[1][2 * oc]     = fmaf(d10, pv1.x, tp[1][2 * oc]);
            tp[1][2 * oc + 1] = fmaf(d11, pv1.y, tp[1][2 * oc + 1]);
        }
    }

    // ================= k-norm + dynamic bias + output =================
    float op0 = 0.0f, op1 = 0.0f;
    #pragma unroll
    for (int oc = 0; oc < 4; oc++) {
        float2 wv  = *(const float2*)&wpb[8 * oc + 2 * q];
        float2 xc0 = *(const float2*)&xs[((mt + 1) * 18 + txr0 + 1) * XST + 8 * oc + 2 * q];
        float2 xc1 = *(const float2*)&xs[((mt + 1) * 18 + txr1 + 1) * XST + 8 * oc + 2 * q];
        op0 = fmaf(tp[0][2 * oc],     rsqrtf(fmaxf(s2[0][2 * oc],     1e-24f)), op0);
        op0 = fmaf(tp[0][2 * oc + 1], rsqrtf(fmaxf(s2[0][2 * oc + 1], 1e-24f)), op0);
        op1 = fmaf(tp[1][2 * oc],     rsqrtf(fmaxf(s2[1][2 * oc],     1e-24f)), op1);
        op1 = fmaf(tp[1][2 * oc + 1], rsqrtf(fmaxf(s2[1][2 * oc + 1], 1e-24f)), op1);
        op0 = fmaf(wv.x, xc0.x, op0);
        op0 = fmaf(wv.y, xc0.y, op0);
        op1 = fmaf(wv.x, xc1.x, op1);
        op1 = fmaf(wv.y, xc1.y, op1);
    }
    op0 += __shfl_xor_sync(0xffffffffu, op0, 1);
    op0 += __shfl_xor_sync(0xffffffffu, op0, 2);
    op1 += __shfl_xor_sync(0xffffffffu, op1, 1);
    op1 += __shfl_xor_sync(0xffffffffu, op1, 2);

    if (q == 0) {
        float* orow = out + (((size_t)b * COUT + o) * HDIM + (y0 + mt)) * WDIM + x0;
        orow[txr0] = op0 + bpo;
        orow[txr1] = op1 + bpo;
    }
}

extern "C" void kernel_launch(void* const* d_in, const int* in_sizes, int n_in,
                              void* d_out, int out_size)
{
    const float* x  = (const float*)d_in[0];   // (2, 32, 64, 64)
    const float* Wp = (const float*)d_in[1];   // (9248, 32)
    const float* bp = (const float*)d_in[2];   // (9248,)
    float* out = (float*)d_out;                // (2, 32, 64, 64)

    cudaFuncSetAttribute(dyn_conv_f16,
                         cudaFuncAttributeMaxDynamicSharedMemorySize, SMEM_BYTES);

    prepass<<<256, 256>>>(x, Wp, bp);

    dim3 grid(WDIM / TN, HDIM / TM, 2 * COUT);   // (4, 8, 64) -> 2048 CTAs
    dyn_conv_f16<<<grid, NTHR, SMEM_BYTES>>>(x, Wp, bp, out);
}

// round 13
// speedup vs baseline: 4.4104x; 1.0506x over previous
#include <cuda_runtime.h>
#include <cuda_fp16.h>
#include <cstdint>

#define CIN   32
#define COUT  32
#define HDIM  64
#define WDIM  64
#define TM    8       // tile rows (y)
#define TN    16      // tile cols (x)
#define NTHR  256
#define XSH   20      // xs_h position stride in u32 words (20g mod 32 distinct -> conflict-free)

// main-kernel smem byte offsets
#define OFF_B    0               // 36 blk * 512B   = 18432   (B f16 fragments)
#define OFF_XH   18432           // 180 pos * 20 u32 = 14400  (half2 halo tile)
#define OFF_BPS  32832           // 288 * 4         = 1152
#define OFF_WPB  33984           // 32 * 4          = 128
#define SMEM_BYTES 34112

typedef unsigned int u32;

// ---- device scratch (precomputed layouts) ----
__device__ u32   BGg[32 * 4608];          // B f16 fragments per o (36 blk * 128 u32)
__device__ float BPSg[32 * 288];          // permuted predictor bias per o
__device__ u32   AGg[2 * 32 * 2048];      // A f16 fragments per (b, tile)
__device__ u32   XHg[2 * 4356 * 16];      // padded x, pixel-major half2: [b][yy*66+xx][c/2]

__device__ __forceinline__ u32 pkh2(float a, float b) {
    __half2 h = __floats2half2_rn(a, b);
    return *(u32*)&h;
}
__device__ __forceinline__ float2 uph2(u32 h) {
    return __half22float2(*(__half2*)&h);
}
__device__ __forceinline__ void mmaf16(float* d, const uint4& a, u32 b0, u32 b1) {
    asm volatile(
        "mma.sync.aligned.m16n8k16.row.col.f32.f16.f16.f32 "
        "{%0,%1,%2,%3}, {%4,%5,%6,%7}, {%8,%9}, {%0,%1,%2,%3};"
        : "+f"(d[0]), "+f"(d[1]), "+f"(d[2]), "+f"(d[3])
        : "r"(a.x), "r"(a.y), "r"(a.z), "r"(a.w), "r"(b0), "r"(b1));
}

// ================= Pre-pass: build all fragment layouts =================
__global__ void prepass(const float* __restrict__ x,
                        const float* __restrict__ Wp,
                        const float* __restrict__ bp)
{
    const u32 t0 = blockIdx.x * blockDim.x + threadIdx.x;
    const u32 stride = gridDim.x * blockDim.x;

    // B f16 fragments: 32 o * 36 blk(kk*4+oc) * 128 u32 (lane*4 + s)
    for (u32 idx = t0; idx < 32u * 4608u; idx += stride) {
        u32 o = idx / 4608u, i = idx - o * 4608u;
        u32 blk = i >> 7, w = i & 127u;
        u32 lane = w >> 2, s = w & 3u;
        u32 g = lane >> 2, q = lane & 3u;
        u32 kk = blk >> 2, oc = blk & 3u;
        u32 ks = s >> 1, r = s & 1u;
        u32 c = 8u * oc + g, cp = 16u * ks + 2u * q + 8u * r;
        const float* row = Wp + ((size_t)o * 288u + c * 9u + kk) * 32u + cp;
        BGg[idx] = pkh2(row[0], row[1]);
    }
    // permuted bias: 32 o * 288
    for (u32 idx = t0; idx < 32u * 288u; idx += stride) {
        u32 o = idx / 288u, j = idx - o * 288u;
        u32 c = j / 9u, kk = j - 9u * c;
        BPSg[o * 288 + kk * 32 + c] = bp[o * 288 + j];
    }
    // A f16 fragments: 2 b * 32 tiles * 16 blk(mtt*2+ks) * 128 u32
    for (u32 idx = t0; idx < 2u * 32u * 2048u; idx += stride) {
        u32 b = idx >> 16;
        u32 i = idx & 65535u;
        u32 tile = i >> 11, j = i & 2047u;
        u32 blk = j >> 7, w = j & 127u;
        u32 lane = w >> 2, s = w & 3u;
        u32 g = lane >> 2, q = lane & 3u;
        u32 mtt = blk >> 1, ks = blk & 1u;
        u32 tiley = tile >> 2, tilex = tile & 3u;
        u32 y = tiley * 8u + mtt;
        u32 xx = tilex * 16u + g + 8u * (s & 1u);
        u32 cp = 16u * ks + 2u * q + 8u * (s >> 1);
        float v0 = x[((size_t)(b * 32 + cp) * HDIM + y) * WDIM + xx];
        float v1 = x[((size_t)(b * 32 + cp + 1) * HDIM + y) * WDIM + xx];
        AGg[idx] = pkh2(v0, v1);
    }
    // padded pixel-major half2 x: 2 b * 66*66 pos * 16 words (c = 2w, 2w+1)
    for (u32 idx = t0; idx < 2u * 4356u * 16u; idx += stride) {
        u32 b = idx / 69696u;
        u32 rest = idx - b * 69696u;
        u32 pos = rest >> 4, w = rest & 15u;
        u32 yy = pos / 66u, xxp = pos - 66u * yy;
        float v0 = 0.0f, v1 = 0.0f;
        if (yy >= 1 && yy <= 64 && xxp >= 1 && xxp <= 64) {
            const float* px = x + ((size_t)(b * 32 + 2 * w) * HDIM + (yy - 1)) * WDIM + (xxp - 1);
            v0 = px[0];
            v1 = px[(size_t)HDIM * WDIM];
        }
        XHg[(size_t)b * 69696u + pos * 16u + w] = pkh2(v0, v1);
    }
}

// ================= Main kernel =================
__global__ __launch_bounds__(NTHR, 2)
void dyn_conv_f16(const float* __restrict__ x,
                  const float* __restrict__ Wp,
                  const float* __restrict__ bp,
                  float* __restrict__ out)
{
    extern __shared__ char sm[];
    u32*   xh  = (u32*)(sm + OFF_XH);
    float* bps = (float*)(sm + OFF_BPS);
    float* wpb = (float*)(sm + OFF_WPB);

    const int bz = blockIdx.z;
    const int b  = bz >> 5;
    const int o  = bz & 31;
    const int x0 = blockIdx.x * TN;
    const int y0 = blockIdx.y * TM;
    const int tid  = threadIdx.x;
    const int lane = tid & 31;
    const int g = lane >> 2;
    const int q = lane & 3;
    const int mt = tid >> 5;       // warp = m-tile (pixel row y0+mt, 16 x-cols)
    const float bpo = bp[9216 + o];

    // ---- A fragments: 2 direct coalesced LDG.128 ----
    uint4 af[2];
    {
        const uint4* Aq = (const uint4*)AGg
            + (size_t)(b * 32 + blockIdx.y * 4 + blockIdx.x) * 512;
        #pragma unroll
        for (int ks = 0; ks < 2; ks++)
            af[ks] = Aq[(mt * 2 + ks) * 32 + lane];
    }

    // ---- B fragments: pure copy global->smem (1152 uint4) ----
    {
        uint4* Bs4 = (uint4*)(sm + OFF_B);
        const uint4* Bg4 = (const uint4*)BGg + (size_t)o * 1152;
        #pragma unroll
        for (int j = 0; j < 5; j++) {
            int i = tid + j * NTHR;
            if (i < 1152) Bs4[i] = Bg4[i];
        }
    }
    // ---- half2 halo tile: 720 uint4 copies from padded image ----
    {
        const uint4* xg4 = (const uint4*)XHg + (size_t)b * 17424;
        #pragma unroll
        for (int j = 0; j < 3; j++) {
            u32 i = tid + j * NTHR;            // need 720
            if (i < 720) {
                u32 pos = i >> 2, c4 = i & 3;
                u32 r = pos / 18u, col = pos - 18u * r;
                uint4 v = xg4[((y0 + r) * 66 + x0 + col) * 4 + c4];
                *(uint4*)&xh[pos * XSH + 4 * c4] = v;
            }
        }
    }
    // ---- bias + wpb copies ----
    for (int i = tid; i < 288; i += NTHR) bps[i] = BPSg[o * 288 + i];
    if (tid < 32) wpb[tid] = Wp[(size_t)(9216 + o) * 32 + tid];
    __syncthreads();

    // ================= Fused single pass over kk =================
    const uint4* Bq = (const uint4*)(sm + OFF_B);
    const int txr0 = g, txr1 = g + 8;
    float s2[2][8], tp[2][8];
    #pragma unroll
    for (int r = 0; r < 2; r++)
        #pragma unroll
        for (int cl = 0; cl < 8; cl++) { s2[r][cl] = 0.0f; tp[r][cl] = 0.0f; }

    #pragma unroll
    for (int kk = 0; kk < 9; kk++) {
        const int dy = kk / 3, dx = kk - 3 * (kk / 3);
        const int pb0 = ((mt + dy) * 18 + txr0 + dx) * XSH + q;
        const int pb1 = ((mt + dy) * 18 + txr1 + dx) * XSH + q;

        // accs initialized with predictor bias (broadcast LDS.64)
        float accT[4][4];
        #pragma unroll
        for (int oc = 0; oc < 4; oc++) {
            float2 bv = *(const float2*)&bps[32 * kk + 8 * oc + 2 * q];
            accT[oc][0] = bv.x; accT[oc][1] = bv.y;
            accT[oc][2] = bv.x; accT[oc][3] = bv.y;
        }
        // 4 independent c-octet tiles, K=32 in 2 f16 k-steps; 1 LDS.128 per (kk,oc)
        #pragma unroll
        for (int oc = 0; oc < 4; oc++) {
            uint4 bb = Bq[(kk * 4 + oc) * 32 + lane];
            mmaf16(accT[oc], af[0], bb.x, bb.y);   // cp 0..15
            mmaf16(accT[oc], af[1], bb.z, bb.w);   // cp 16..31
        }
        // c-norm: per-thread partials + quad reduce (all 32 c live in-warp)
        float s1r0 = 0.0f, s1r1 = 0.0f;
        #pragma unroll
        for (int oc = 0; oc < 4; oc++) {
            s1r0 = fmaf(accT[oc][0], accT[oc][0], s1r0);
            s1r0 = fmaf(accT[oc][1], accT[oc][1], s1r0);
            s1r1 = fmaf(accT[oc][2], accT[oc][2], s1r1);
            s1r1 = fmaf(accT[oc][3], accT[oc][3], s1r1);
        }
        s1r0 += __shfl_xor_sync(0xffffffffu, s1r0, 1);
        s1r0 += __shfl_xor_sync(0xffffffffu, s1r0, 2);
        s1r1 += __shfl_xor_sync(0xffffffffu, s1r1, 1);
        s1r1 += __shfl_xor_sync(0xffffffffu, s1r1, 2);
        float inv1r0 = rsqrtf(fmaxf(s1r0, 1e-24f));   // == 1/max(sqrt,1e-12)
        float inv1r1 = rsqrtf(fmaxf(s1r1, 1e-24f));

        // scale by inv1; accumulate s2[c] and patch contraction (LDS.32 half2 pv)
        #pragma unroll
        for (int oc = 0; oc < 4; oc++) {
            float2 pv0 = uph2(xh[pb0 + 4 * oc]);   // conflict-free: banks 20g+4oc+q
            float2 pv1 = uph2(xh[pb1 + 4 * oc]);
            float d00 = accT[oc][0] * inv1r0;
            float d01 = accT[oc][1] * inv1r0;
            float d10 = accT[oc][2] * inv1r1;
            float d11 = accT[oc][3] * inv1r1;
            s2[0][2 * oc]     = fmaf(d00, d00, s2[0][2 * oc]);
            s2[0][2 * oc + 1] = fmaf(d01, d01, s2[0][2 * oc + 1]);
            s2[1][2 * oc]     = fmaf(d10, d10, s2[1][2 * oc]);
            s2[1][2 * oc + 1] = fmaf(d11, d11, s2[1][2 * oc + 1]);
            tp[0][2 * oc]     = fmaf(d00, pv0.x, tp[0][2 * oc]);
            tp[0][2 * oc + 1] = fmaf(d01, pv0.y, tp[0][2 * oc + 1]);
            tp[1][2 * oc]     = fmaf(d10, pv1.x, tp[1][2 * oc]);
            tp[1][2 * oc + 1] = fmaf(d11, pv1.y, tp[1][2 * oc + 1]);
        }
    }

    // ================= k-norm + dynamic bias + output =================
    const int cb0 = ((mt + 1) * 18 + txr0 + 1) * XSH + q;
    const int cb1 = ((mt + 1) * 18 + txr1 + 1) * XSH + q;
    float op0 = 0.0f, op1 = 0.0f;
    #pragma unroll
    for (int oc = 0; oc < 4; oc++) {
        float2 wv  = *(const float2*)&wpb[8 * oc + 2 * q];
        float2 xc0 = uph2(xh[cb0 + 4 * oc]);
        float2 xc1 = uph2(xh[cb1 + 4 * oc]);
        op0 = fmaf(tp[0][2 * oc],     rsqrtf(fmaxf(s2[0][2 * oc],     1e-24f)), op0);
        op0 = fmaf(tp[0][2 * oc + 1], rsqrtf(fmaxf(s2[0][2 * oc + 1], 1e-24f)), op0);
        op1 = fmaf(tp[1][2 * oc],     rsqrtf(fmaxf(s2[1][2 * oc],     1e-24f)), op1);
        op1 = fmaf(tp[1][2 * oc + 1], rsqrtf(fmaxf(s2[1][2 * oc + 1], 1e-24f)), op1);
        op0 = fmaf(wv.x, xc0.x, op0);
        op0 = fmaf(wv.y, xc0.y, op0);
        op1 = fmaf(wv.x, xc1.x, op1);
        op1 = fmaf(wv.y, xc1.y, op1);
    }
    op0 += __shfl_xor_sync(0xffffffffu, op0, 1);
    op0 += __shfl_xor_sync(0xffffffffu, op0, 2);
    op1 += __shfl_xor_sync(0xffffffffu, op1, 1);
    op1 += __shfl_xor_sync(0xffffffffu, op1, 2);

    if (q == 0) {
        float* orow = out + (((size_t)b * COUT + o) * HDIM + (y0 + mt)) * WDIM + x0;
        orow[txr0] = op0 + bpo;
        orow[txr1] = op1 + bpo;
    }
}

extern "C" void kernel_launch(void* const* d_in, const int* in_sizes, int n_in,
                              void* d_out, int out_size)
{
    const float* x  = (const float*)d_in[0];   // (2, 32, 64, 64)
    const float* Wp = (const float*)d_in[1];   // (9248, 32)
    const float* bp = (const float*)d_in[2];   // (9248,)
    float* out = (float*)d_out;                // (2, 32, 64, 64)

    cudaFuncSetAttribute(dyn_conv_f16,
                         cudaFuncAttributeMaxDynamicSharedMemorySize, SMEM_BYTES);

    prepass<<<256, 256>>>(x, Wp, bp);

    dim3 grid(WDIM / TN, HDIM / TM, 2 * COUT);   // (4, 8, 64) -> 2048 CTAs
    dyn_conv_f16<<<grid, NTHR, SMEM_BYTES>>>(x, Wp, bp, out);
}